// round 1
// baseline (speedup 1.0000x reference)
#include <cuda_runtime.h>

#define BATCH 64

// conv1: 3 -> 64, 224x224 -> 112x112, stride 2, SAME (pad_low=0, pad_high=1)
// conv2: 64 -> 128, 112x112 -> 56x56,  stride 2, SAME (pad_low=0, pad_high=1)

// Scratch: conv1 output (post-ReLU), reused for both experts sequentially.
__device__ float g_h1[BATCH * 64 * 112 * 112];          // 205 MB
// Partial pooled sums: [expert 2][b 64][ocb 8][blk 13][oc 16]
__device__ float g_partial[2 * BATCH * 8 * 13 * 16];

// ---------------------------------------------------------------------------
// conv1 + ReLU: block = 256 threads, each thread = one output pixel, all 64 oc
// grid = (49, BATCH)   (49*256 = 12544 = 112*112 exactly)
// ---------------------------------------------------------------------------
__global__ __launch_bounds__(256) void conv1_kernel(const float* __restrict__ x,
                                                    const float* __restrict__ w,
                                                    const float* __restrict__ bias)
{
    __shared__ float ws[27 * 64];   // [k 27][oc 64]
    __shared__ float bs[64];
    const int tid = threadIdx.x;
    const int b = blockIdx.y;

    for (int i = tid; i < 27 * 64; i += 256) {
        int oc = i / 27, k = i % 27;
        ws[k * 64 + oc] = w[i];
    }
    if (tid < 64) bs[tid] = bias[tid];
    __syncthreads();

    const int pos = blockIdx.x * 256 + tid;    // 0..12543
    const int oh = pos / 112, ow = pos % 112;
    const int ih0 = oh * 2, iw0 = ow * 2;
    const bool bh = (oh < 111), bw = (ow < 111);

    float in[27];
    const float* xb = x + (size_t)b * (3 * 224 * 224);
    #pragma unroll
    for (int ic = 0; ic < 3; ++ic) {
        const float* p = xb + ic * (224 * 224) + ih0 * 224 + iw0;
        #pragma unroll
        for (int kh = 0; kh < 3; ++kh) {
            #pragma unroll
            for (int kw = 0; kw < 3; ++kw) {
                bool ok = (kh < 2 || bh) && (kw < 2 || bw);
                in[ic * 9 + kh * 3 + kw] = ok ? p[kh * 224 + kw] : 0.0f;
            }
        }
    }

    float* outb = g_h1 + (size_t)b * (64 * 112 * 112) + pos;
    #pragma unroll
    for (int occ = 0; occ < 4; ++occ) {
        float acc[16];
        #pragma unroll
        for (int j = 0; j < 16; ++j) acc[j] = bs[occ * 16 + j];
        #pragma unroll
        for (int k = 0; k < 27; ++k) {
            const float v = in[k];
            const float4* wr = (const float4*)(ws + k * 64 + occ * 16);
            #pragma unroll
            for (int q = 0; q < 4; ++q) {
                float4 wq = wr[q];
                acc[4 * q + 0] = fmaf(v, wq.x, acc[4 * q + 0]);
                acc[4 * q + 1] = fmaf(v, wq.y, acc[4 * q + 1]);
                acc[4 * q + 2] = fmaf(v, wq.z, acc[4 * q + 2]);
                acc[4 * q + 3] = fmaf(v, wq.w, acc[4 * q + 3]);
            }
        }
        #pragma unroll
        for (int j = 0; j < 16; ++j)
            outb[(size_t)(occ * 16 + j) * (112 * 112)] = fmaxf(acc[j], 0.0f);
    }
}

// ---------------------------------------------------------------------------
// conv2 + ReLU + partial global-average-pool (deterministic block reduction)
// grid = (13, 8, BATCH): blockIdx.x = position chunk (3136 pos, 256/blk),
//                        blockIdx.y = oc chunk of 16, blockIdx.z = batch
// ---------------------------------------------------------------------------
__global__ __launch_bounds__(256) void conv2_pool_kernel(const float* __restrict__ w,
                                                         const float* __restrict__ bias,
                                                         int expert)
{
    __shared__ float ws[64 * 9 * 16];   // [(ic*9+k)][oc 16]
    __shared__ float wsum[8 * 16];      // [warp][oc]
    const int tid = threadIdx.x;
    const int b = blockIdx.z;
    const int ocb = blockIdx.y;
    const int ocbase = ocb * 16;

    for (int i = tid; i < 16 * 576; i += 256) {
        int oc = i / 576, r = i % 576;
        ws[r * 16 + oc] = w[(ocbase + oc) * 576 + r];
    }
    __syncthreads();

    const int pos = blockIdx.x * 256 + tid;
    const bool valid = (pos < 3136);
    int oh = valid ? pos / 56 : 0;
    int ow = valid ? pos % 56 : 0;
    const int ih0 = oh * 2, iw0 = ow * 2;
    const bool bh = (oh < 55), bw = (ow < 55);

    float acc[16];
    #pragma unroll
    for (int j = 0; j < 16; ++j) acc[j] = bias[ocbase + j];

    const float* inb = g_h1 + (size_t)b * (64 * 112 * 112) + ih0 * 112 + iw0;
    for (int ic = 0; ic < 64; ++ic) {
        const float* p = inb + ic * (112 * 112);
        float in[9];
        #pragma unroll
        for (int kh = 0; kh < 3; ++kh) {
            #pragma unroll
            for (int kw = 0; kw < 3; ++kw) {
                bool ok = (kh < 2 || bh) && (kw < 2 || bw);
                in[kh * 3 + kw] = ok ? p[kh * 112 + kw] : 0.0f;
            }
        }
        const float4* wr = (const float4*)(ws + ic * 144);
        #pragma unroll
        for (int k = 0; k < 9; ++k) {
            const float v = in[k];
            #pragma unroll
            for (int q = 0; q < 4; ++q) {
                float4 wq = wr[4 * k + q];
                acc[4 * q + 0] = fmaf(v, wq.x, acc[4 * q + 0]);
                acc[4 * q + 1] = fmaf(v, wq.y, acc[4 * q + 1]);
                acc[4 * q + 2] = fmaf(v, wq.z, acc[4 * q + 2]);
                acc[4 * q + 3] = fmaf(v, wq.w, acc[4 * q + 3]);
            }
        }
    }

    // ReLU + deterministic reduction over the block's positions
    const int lane = tid & 31, warp = tid >> 5;
    #pragma unroll
    for (int j = 0; j < 16; ++j) {
        float v = valid ? fmaxf(acc[j], 0.0f) : 0.0f;
        #pragma unroll
        for (int s = 16; s > 0; s >>= 1)
            v += __shfl_down_sync(0xffffffffu, v, s);
        if (lane == 0) wsum[warp * 16 + j] = v;
    }
    __syncthreads();
    if (tid < 16) {
        float s = 0.0f;
        #pragma unroll
        for (int wg = 0; wg < 8; ++wg) s += wsum[wg * 16 + tid];
        g_partial[((((size_t)expert * BATCH + b) * 8 + ocb) * 13 + blockIdx.x) * 16 + tid] = s;
    }
}

// ---------------------------------------------------------------------------
// head: reduce partials -> GAP -> FC -> softmax confidence -> blend + freq
// one block, 64 threads (one per batch row)
// ---------------------------------------------------------------------------
__global__ void head_kernel(const float* __restrict__ t_wf, const float* __restrict__ t_bf,
                            const float* __restrict__ f_wf, const float* __restrict__ f_bf,
                            float* __restrict__ out, int out_size)
{
    __shared__ int cnt;
    const int b = threadIdx.x;   // 0..63
    if (b == 0) cnt = 0;
    __syncthreads();

    const float inv = 1.0f / 3136.0f;
    float tl0 = t_bf[0], tl1 = t_bf[1];
    float fl0 = f_bf[0], fl1 = f_bf[1];
    const size_t fofs = (size_t)BATCH * 8 * 13 * 16;

    for (int c = 0; c < 128; ++c) {
        const size_t base = ((size_t)(b * 8 + (c >> 4)) * 13) * 16 + (c & 15);
        float st = 0.0f, sf = 0.0f;
        #pragma unroll
        for (int xk = 0; xk < 13; ++xk) {
            st += g_partial[base + (size_t)xk * 16];
            sf += g_partial[fofs + base + (size_t)xk * 16];
        }
        const float gt = st * inv;
        const float gf = sf * inv;
        tl0 = fmaf(gt, t_wf[c * 2 + 0], tl0);
        tl1 = fmaf(gt, t_wf[c * 2 + 1], tl1);
        fl0 = fmaf(gf, f_wf[c * 2 + 0], fl0);
        fl1 = fmaf(gf, f_wf[c * 2 + 1], fl1);
    }

    const float m = fmaxf(tl0, tl1);
    const float e0 = expf(tl0 - m), e1 = expf(tl1 - m);
    const float conf = fmaxf(e0, e1) / (e0 + e1);
    const bool use2 = (conf <= 0.9f);

    out[b * 2 + 0] = use2 ? 0.7f * tl0 + 0.3f * fl0 : tl0;
    out[b * 2 + 1] = use2 ? 0.7f * tl1 + 0.3f * fl1 : tl1;

    if (use2) atomicAdd(&cnt, 1);
    __syncthreads();
    if (b == 0 && out_size > 128) out[128] = (float)cnt * (1.0f / 64.0f);
}

// ---------------------------------------------------------------------------
extern "C" void kernel_launch(void* const* d_in, const int* in_sizes, int n_in,
                              void* d_out, int out_size)
{
    const float* x    = (const float*)d_in[0];
    const float* t_w1 = (const float*)d_in[1];
    const float* t_b1 = (const float*)d_in[2];
    const float* t_w2 = (const float*)d_in[3];
    const float* t_b2 = (const float*)d_in[4];
    const float* t_wf = (const float*)d_in[5];
    const float* t_bf = (const float*)d_in[6];
    const float* f_w1 = (const float*)d_in[7];
    const float* f_b1 = (const float*)d_in[8];
    const float* f_w2 = (const float*)d_in[9];
    const float* f_b2 = (const float*)d_in[10];
    const float* f_wf = (const float*)d_in[11];
    const float* f_bf = (const float*)d_in[12];
    float* out = (float*)d_out;

    dim3 g1(49, BATCH);
    dim3 g2(13, 8, BATCH);

    // texture expert
    conv1_kernel<<<g1, 256>>>(x, t_w1, t_b1);
    conv2_pool_kernel<<<g2, 256>>>(t_w2, t_b2, 0);
    // frequency expert (reuses g_h1; same-stream ordering serializes)
    conv1_kernel<<<g1, 256>>>(x, f_w1, f_b1);
    conv2_pool_kernel<<<g2, 256>>>(f_w2, f_b2, 1);
    // head
    head_kernel<<<1, 64>>>(t_wf, t_bf, f_wf, f_bf, out, out_size);
}

// round 2
// speedup vs baseline: 1.7611x; 1.7611x over previous
#include <cuda_runtime.h>

#define BATCH 64

typedef unsigned long long ull;

__device__ __forceinline__ ull pack2(float lo, float hi) {
    ull r; asm("mov.b64 %0, {%1,%2};" : "=l"(r) : "f"(lo), "f"(hi)); return r;
}
__device__ __forceinline__ void unpack2(ull v, float& lo, float& hi) {
    asm("mov.b64 {%0,%1}, %2;" : "=f"(lo), "=f"(hi) : "l"(v));
}
__device__ __forceinline__ ull fma2(ull a, ull b, ull c) {
    ull d; asm("fma.rn.f32x2 %0, %1, %2, %3;" : "=l"(d) : "l"(a), "l"(b), "l"(c)); return d;
}

// conv1: 3 -> 64, 224x224 -> 112x112, stride 2, SAME (pad_low=0, pad_high=1)
// conv2: 64 -> 128, 112x112 -> 56x56,  stride 2, SAME (pad_low=0, pad_high=1)

__device__ float g_h1[BATCH * 64 * 112 * 112];          // 205 MB scratch
// Partial pooled sums: [expert 2][b 64][ocb 8][blk 7][oc 16]
__device__ float g_partial[2 * BATCH * 8 * 7 * 16];

// ---------------------------------------------------------------------------
// conv1 + ReLU (f32x2): 256 threads, one output pixel each, all 64 oc
// grid = (49, BATCH)
// ---------------------------------------------------------------------------
__global__ __launch_bounds__(256) void conv1_kernel(const float* __restrict__ x,
                                                    const float* __restrict__ w,
                                                    const float* __restrict__ bias)
{
    __shared__ float ws[27 * 64];   // [k 27][oc 64]
    __shared__ float bs[64];
    const int tid = threadIdx.x;
    const int b = blockIdx.y;

    for (int i = tid; i < 27 * 64; i += 256) {
        int oc = i / 27, k = i % 27;
        ws[k * 64 + oc] = w[i];
    }
    if (tid < 64) bs[tid] = bias[tid];
    __syncthreads();

    const int pos = blockIdx.x * 256 + tid;    // 0..12543
    const int oh = pos / 112, ow = pos % 112;
    const int ih0 = oh * 2, iw0 = ow * 2;
    const bool bh = (oh < 111), bw = (ow < 111);

    ull pin[27];
    const float* xb = x + (size_t)b * (3 * 224 * 224);
    #pragma unroll
    for (int ic = 0; ic < 3; ++ic) {
        const float* p = xb + ic * (224 * 224) + ih0 * 224 + iw0;
        #pragma unroll
        for (int kh = 0; kh < 3; ++kh) {
            #pragma unroll
            for (int kw = 0; kw < 3; ++kw) {
                bool ok = (kh < 2 || bh) && (kw < 2 || bw);
                float v = ok ? p[kh * 224 + kw] : 0.0f;
                pin[ic * 9 + kh * 3 + kw] = pack2(v, v);
            }
        }
    }

    float* outb = g_h1 + (size_t)b * (64 * 112 * 112) + pos;
    #pragma unroll
    for (int occ = 0; occ < 4; ++occ) {
        ull acc[8];
        #pragma unroll
        for (int j = 0; j < 8; ++j)
            acc[j] = pack2(bs[occ * 16 + 2 * j], bs[occ * 16 + 2 * j + 1]);
        #pragma unroll
        for (int k = 0; k < 27; ++k) {
            const ull* w2 = (const ull*)(ws + k * 64 + occ * 16);
            #pragma unroll
            for (int j = 0; j < 8; ++j)
                acc[j] = fma2(pin[k], w2[j], acc[j]);
        }
        #pragma unroll
        for (int j = 0; j < 8; ++j) {
            float lo, hi; unpack2(acc[j], lo, hi);
            outb[(size_t)(occ * 16 + 2 * j) * (112 * 112)]     = fmaxf(lo, 0.0f);
            outb[(size_t)(occ * 16 + 2 * j + 1) * (112 * 112)] = fmaxf(hi, 0.0f);
        }
    }
}

// ---------------------------------------------------------------------------
// conv2 + ReLU + partial GAP, f32x2, 4 oh-positions x 16 oc per thread.
// block = 128: ow = tid&63 (active<56), ty = tid>>6; oh0 = bx*8 + ty*4
// grid = (7, 8 ocb, BATCH)
// ---------------------------------------------------------------------------
__global__ __launch_bounds__(128, 4) void conv2_pool_kernel(const float* __restrict__ w,
                                                            const float* __restrict__ bias,
                                                            int expert)
{
    __shared__ float ws[64 * 9 * 16];   // [(ic*9+k)][oc 16]
    __shared__ float wsum[4 * 16];      // [warp][oc]
    const int tid = threadIdx.x;
    const int b = blockIdx.z;
    const int ocb = blockIdx.y;
    const int ocbase = ocb * 16;

    for (int i = tid; i < 16 * 576; i += 128) {
        int oc = i / 576, r = i % 576;
        ws[r * 16 + oc] = w[(ocbase + oc) * 576 + r];
    }
    __syncthreads();

    const int ow = tid & 63;
    const int ty = tid >> 6;
    const int oh0 = blockIdx.x * 8 + ty * 4;     // positions oh0..oh0+3
    const bool act = (ow < 56);
    const int iw0 = ow * 2;
    const int ir0 = oh0 * 2;                     // input rows ir0..ir0+8

    // column validity (iw0+c < 112); row validity (ir0+r < 112)
    bool colok[3], rowok[9];
    #pragma unroll
    for (int c = 0; c < 3; ++c) colok[c] = act && (iw0 + c < 112);
    #pragma unroll
    for (int r = 0; r < 9; ++r) rowok[r] = (ir0 + r < 112);

    ull acc[4][8];
    #pragma unroll
    for (int p = 0; p < 4; ++p)
        #pragma unroll
        for (int j = 0; j < 8; ++j)
            acc[p][j] = pack2(bias[ocbase + 2 * j], bias[ocbase + 2 * j + 1]);

    const float* inb = g_h1 + (size_t)b * (64 * 112 * 112) + ir0 * 112 + iw0;
    for (int ic = 0; ic < 64; ++ic) {
        const float* p = inb + ic * (112 * 112);
        float in[9][3];
        #pragma unroll
        for (int r = 0; r < 9; ++r) {
            #pragma unroll
            for (int c = 0; c < 3; ++c)
                in[r][c] = (rowok[r] && colok[c]) ? p[r * 112 + c] : 0.0f;
        }
        #pragma unroll
        for (int kh = 0; kh < 3; ++kh) {
            #pragma unroll
            for (int kw = 0; kw < 3; ++kw) {
                const int k = kh * 3 + kw;
                const ull* w2 = (const ull*)(ws + (ic * 9 + k) * 16);
                ull wv[8];
                #pragma unroll
                for (int j = 0; j < 8; ++j) wv[j] = w2[j];
                #pragma unroll
                for (int pp = 0; pp < 4; ++pp) {
                    const float v = in[2 * pp + kh][kw];
                    const ull vv = pack2(v, v);
                    #pragma unroll
                    for (int j = 0; j < 8; ++j)
                        acc[pp][j] = fma2(vv, wv[j], acc[pp][j]);
                }
            }
        }
    }

    // ReLU per position, sum 4 positions -> 16 scalars per thread
    float s[16];
    #pragma unroll
    for (int j = 0; j < 16; ++j) s[j] = 0.0f;
    if (act) {
        #pragma unroll
        for (int pp = 0; pp < 4; ++pp) {
            #pragma unroll
            for (int j = 0; j < 8; ++j) {
                float lo, hi; unpack2(acc[pp][j], lo, hi);
                s[2 * j]     += fmaxf(lo, 0.0f);
                s[2 * j + 1] += fmaxf(hi, 0.0f);
            }
        }
    }

    // deterministic reduction: warp shuffles -> smem -> 16 threads
    const int lane = tid & 31, warp = tid >> 5;
    #pragma unroll
    for (int j = 0; j < 16; ++j) {
        float v = s[j];
        #pragma unroll
        for (int sh = 16; sh > 0; sh >>= 1)
            v += __shfl_down_sync(0xffffffffu, v, sh);
        if (lane == 0) wsum[warp * 16 + j] = v;
    }
    __syncthreads();
    if (tid < 16) {
        float t = 0.0f;
        #pragma unroll
        for (int wg = 0; wg < 4; ++wg) t += wsum[wg * 16 + tid];
        g_partial[((((size_t)expert * BATCH + b) * 8 + ocb) * 7 + blockIdx.x) * 16 + tid] = t;
    }
}

// ---------------------------------------------------------------------------
// head: reduce partials -> GAP -> FC -> softmax confidence -> blend + freq
// ---------------------------------------------------------------------------
__global__ void head_kernel(const float* __restrict__ t_wf, const float* __restrict__ t_bf,
                            const float* __restrict__ f_wf, const float* __restrict__ f_bf,
                            float* __restrict__ out, int out_size)
{
    __shared__ int cnt;
    const int b = threadIdx.x;   // 0..63
    if (b == 0) cnt = 0;
    __syncthreads();

    const float inv = 1.0f / 3136.0f;
    float tl0 = t_bf[0], tl1 = t_bf[1];
    float fl0 = f_bf[0], fl1 = f_bf[1];
    const size_t fofs = (size_t)BATCH * 8 * 7 * 16;

    for (int c = 0; c < 128; ++c) {
        const size_t base = ((size_t)(b * 8 + (c >> 4)) * 7) * 16 + (c & 15);
        float st = 0.0f, sf = 0.0f;
        #pragma unroll
        for (int xk = 0; xk < 7; ++xk) {
            st += g_partial[base + (size_t)xk * 16];
            sf += g_partial[fofs + base + (size_t)xk * 16];
        }
        const float gt = st * inv;
        const float gf = sf * inv;
        tl0 = fmaf(gt, t_wf[c * 2 + 0], tl0);
        tl1 = fmaf(gt, t_wf[c * 2 + 1], tl1);
        fl0 = fmaf(gf, f_wf[c * 2 + 0], fl0);
        fl1 = fmaf(gf, f_wf[c * 2 + 1], fl1);
    }

    const float m = fmaxf(tl0, tl1);
    const float e0 = expf(tl0 - m), e1 = expf(tl1 - m);
    const float conf = fmaxf(e0, e1) / (e0 + e1);
    const bool use2 = (conf <= 0.9f);

    out[b * 2 + 0] = use2 ? 0.7f * tl0 + 0.3f * fl0 : tl0;
    out[b * 2 + 1] = use2 ? 0.7f * tl1 + 0.3f * fl1 : tl1;

    if (use2) atomicAdd(&cnt, 1);
    __syncthreads();
    if (b == 0 && out_size > 128) out[128] = (float)cnt * (1.0f / 64.0f);
}

// ---------------------------------------------------------------------------
extern "C" void kernel_launch(void* const* d_in, const int* in_sizes, int n_in,
                              void* d_out, int out_size)
{
    const float* x    = (const float*)d_in[0];
    const float* t_w1 = (const float*)d_in[1];
    const float* t_b1 = (const float*)d_in[2];
    const float* t_w2 = (const float*)d_in[3];
    const float* t_b2 = (const float*)d_in[4];
    const float* t_wf = (const float*)d_in[5];
    const float* t_bf = (const float*)d_in[6];
    const float* f_w1 = (const float*)d_in[7];
    const float* f_b1 = (const float*)d_in[8];
    const float* f_w2 = (const float*)d_in[9];
    const float* f_b2 = (const float*)d_in[10];
    const float* f_wf = (const float*)d_in[11];
    const float* f_bf = (const float*)d_in[12];
    float* out = (float*)d_out;

    dim3 g1(49, BATCH);
    dim3 g2(7, 8, BATCH);

    conv1_kernel<<<g1, 256>>>(x, t_w1, t_b1);
    conv2_pool_kernel<<<g2, 128>>>(t_w2, t_b2, 0);
    conv1_kernel<<<g1, 256>>>(x, f_w1, f_b1);
    conv2_pool_kernel<<<g2, 128>>>(f_w2, f_b2, 1);
    head_kernel<<<1, 64>>>(t_wf, t_bf, f_wf, f_bf, out, out_size);
}

// round 4
// speedup vs baseline: 2.0219x; 1.1481x over previous
#include <cuda_runtime.h>
#include <cstdint>

#define BATCH 64
typedef unsigned long long ull;
typedef uint32_t u32;

// ---------------------------------------------------------------------------
// Device scratch
// ---------------------------------------------------------------------------
__device__ float g_h1[2ULL * BATCH * 112 * 112 * 64];   // NHWC (ic-permuted, tf32-rounded)
__device__ float g_w2t[2 * 9 * 128 * 64];               // [e][tap][oc][ic-permuted], tf32
__device__ float g_partial[2 * BATCH * 28 * 128];       // pooled partials per M-tile

// ---------------------------------------------------------------------------
// helpers
// ---------------------------------------------------------------------------
__device__ __forceinline__ ull pack2(float lo, float hi) {
    ull r; asm("mov.b64 %0, {%1,%2};" : "=l"(r) : "f"(lo), "f"(hi)); return r;
}
__device__ __forceinline__ void unpack2(ull v, float& lo, float& hi) {
    asm("mov.b64 {%0,%1}, %2;" : "=f"(lo), "=f"(hi) : "l"(v));
}
__device__ __forceinline__ ull fma2(ull a, ull b, ull c) {
    ull d; asm("fma.rn.f32x2 %0, %1, %2, %3;" : "=l"(d) : "l"(a), "l"(b), "l"(c)); return d;
}
__device__ __forceinline__ float to_tf32(float f) {
    u32 r; asm("cvt.rna.tf32.f32 %0, %1;" : "=r"(r) : "f"(f));
    return __uint_as_float(r);
}
__device__ __forceinline__ u32 smem_u32(const void* p) {
    return (u32)__cvta_generic_to_shared(p);
}
__device__ __forceinline__ void cp16(u32 dst, const void* src) {
    asm volatile("cp.async.cg.shared.global [%0], [%1], 16;" :: "r"(dst), "l"(src));
}
__device__ __forceinline__ void cp_commit() {
    asm volatile("cp.async.commit_group;" ::: "memory");
}
template<int N> __device__ __forceinline__ void cp_wait() {
    asm volatile("cp.async.wait_group %0;" :: "n"(N) : "memory");
}
__device__ __forceinline__ void lds2(u32& x, u32& y, u32 addr) {
    asm volatile("ld.shared.v2.b32 {%0,%1}, [%2];" : "=r"(x), "=r"(y) : "r"(addr));
}
__device__ __forceinline__ void mma_tf32(float* c, u32 a0, u32 a1, u32 a2, u32 a3,
                                         u32 b0, u32 b1) {
    asm volatile(
        "mma.sync.aligned.m16n8k8.row.col.f32.tf32.tf32.f32 "
        "{%0,%1,%2,%3}, {%4,%5,%6,%7}, {%8,%9}, {%0,%1,%2,%3};"
        : "+f"(c[0]), "+f"(c[1]), "+f"(c[2]), "+f"(c[3])
        : "r"(a0), "r"(a1), "r"(a2), "r"(a3), "r"(b0), "r"(b1));
}

// ic permutation: stored position p holds original channel l(p) so that mma's
// (k, k+4) fragment pair is a contiguous 64-bit load. Within each 8-group:
// l(p) = (p>>1) + (p&1)*4.
__device__ __forceinline__ int perm_src(int p) {
    return (p & ~7) | (((p & 7) >> 1) + ((p & 1) << 2));
}

// ---------------------------------------------------------------------------
// prep: transpose conv2 weights [oc][ic][kh][kw] -> [e][tap][oc][icp] (tf32)
// ---------------------------------------------------------------------------
__global__ void prep_w2(const float* __restrict__ tw2, const float* __restrict__ fw2)
{
    const int i = blockIdx.x * 256 + threadIdx.x;   // < 2*9*128*64 = 147456
    const int e = i / 73728;
    const int r = i - e * 73728;
    const int tap = r / 8192;
    const int r2 = r - tap * 8192;
    const int oc = r2 >> 6, icp = r2 & 63;
    const int ic = perm_src(icp);
    const float* w = e ? fw2 : tw2;
    g_w2t[i] = to_tf32(w[oc * 576 + ic * 9 + tap]);
}

// ---------------------------------------------------------------------------
// conv1 + ReLU (f32x2) -> NHWC permuted tf32. grid=(49, BATCH, 2), 256 thr
// ---------------------------------------------------------------------------
__global__ __launch_bounds__(256) void conv1_kernel(const float* __restrict__ x,
                                                    const float* __restrict__ wt,
                                                    const float* __restrict__ bt,
                                                    const float* __restrict__ wf,
                                                    const float* __restrict__ bf)
{
    __shared__ float ws[27 * 64];   // [k 27][oc 64]
    __shared__ float bs[64];
    const int tid = threadIdx.x;
    const int b = blockIdx.y, e = blockIdx.z;
    const float* w = e ? wf : wt;
    const float* bias = e ? bf : bt;

    for (int i = tid; i < 27 * 64; i += 256) {
        int oc = i / 27, k = i % 27;
        ws[k * 64 + oc] = w[i];
    }
    if (tid < 64) bs[tid] = bias[tid];
    __syncthreads();

    const int pos = blockIdx.x * 256 + tid;    // 0..12543
    const int oh = pos / 112, ow = pos % 112;
    const int ih0 = oh * 2, iw0 = ow * 2;
    const bool bh = (oh < 111), bw = (ow < 111);

    ull pin[27];
    const float* xb = x + (size_t)b * (3 * 224 * 224);
    #pragma unroll
    for (int ic = 0; ic < 3; ++ic) {
        const float* p = xb + ic * (224 * 224) + ih0 * 224 + iw0;
        #pragma unroll
        for (int kh = 0; kh < 3; ++kh) {
            #pragma unroll
            for (int kw = 0; kw < 3; ++kw) {
                bool ok = (kh < 2 || bh) && (kw < 2 || bw);
                float v = ok ? p[kh * 224 + kw] : 0.0f;
                pin[ic * 9 + kh * 3 + kw] = pack2(v, v);
            }
        }
    }

    float4* outb = (float4*)(g_h1 + ((size_t)(e * BATCH + b) * 12544 + pos) * 64);
    #pragma unroll
    for (int occ = 0; occ < 4; ++occ) {
        ull acc[8];
        #pragma unroll
        for (int j = 0; j < 8; ++j)
            acc[j] = pack2(bs[occ * 16 + 2 * j], bs[occ * 16 + 2 * j + 1]);
        #pragma unroll
        for (int k = 0; k < 27; ++k) {
            const ull* w2 = (const ull*)(ws + k * 64 + occ * 16);
            #pragma unroll
            for (int j = 0; j < 8; ++j)
                acc[j] = fma2(pin[k], w2[j], acc[j]);
        }
        float ov[16];
        #pragma unroll
        for (int j = 0; j < 8; ++j) {
            float lo, hi; unpack2(acc[j], lo, hi);
            ov[2 * j]     = fmaxf(lo, 0.0f);
            ov[2 * j + 1] = fmaxf(hi, 0.0f);
        }
        #pragma unroll
        for (int q = 0; q < 4; ++q) {
            float v0 = to_tf32(ov[perm_src(4 * q + 0) & 15]);
            float v1 = to_tf32(ov[perm_src(4 * q + 1) & 15]);
            float v2 = to_tf32(ov[perm_src(4 * q + 2) & 15]);
            float v3 = to_tf32(ov[perm_src(4 * q + 3) & 15]);
            outb[occ * 4 + q] = make_float4(v0, v1, v2, v3);
        }
    }
}

// ---------------------------------------------------------------------------
// conv2: implicit GEMM on mma.sync tf32 + fused bias/ReLU/GAP epilogue.
// Tile M=128 (2 oh x 64 ow; ow>=56 padded), N=128 oc, K=9 taps x 64 ic.
// 8 warps: warp tile 32x64 (4 M x 2 N grid). grid=(28, BATCH, 2), 256 thr.
// SMEM: A/B tiles 128 rows x 72-float stride (288B), double-buffered by tap.
// ---------------------------------------------------------------------------
#define AST       36864              // one A stage: 128*288
#define SMEM_B0   73728              // B stages at 73728
#define SMEM_MISC 147456
#define SMEM_TOTAL (147456 + 512 + 4096)

__global__ __launch_bounds__(256, 1) void conv2_kernel(const float* __restrict__ bias_t,
                                                       const float* __restrict__ bias_f)
{
    extern __shared__ __align__(256) char smem[];
    const int tid = threadIdx.x;
    const int wid = tid >> 5, lane = tid & 31;
    const int tile = blockIdx.x, b = blockIdx.y, e = blockIdx.z;
    const u32 sb = smem_u32(smem);

    float* bias_s = (float*)(smem + SMEM_MISC);
    float* wsum   = (float*)(smem + SMEM_MISC + 512);   // [8 warps][128]

    if (tid < 128) bias_s[tid] = (e ? bias_f : bias_t)[tid];

    // ---- load mapping: 2 threads per row, 8 x 16B chunks each
    const int m = tid >> 1;           // row 0..127
    const int half = tid & 1;
    const int ohl = m >> 6, owl = m & 63;
    const size_t img = (size_t)(e * BATCH + b) * (112 * 112 * 64);
    const float* wt_base = g_w2t + (size_t)e * (9 * 128 * 64) + (size_t)m * 64 + half * 32;
    const u32 a_row = sb + m * 288 + half * 128;
    const u32 b_row = sb + SMEM_B0 + m * 288 + half * 128;

    auto load_tap = [&](int tap, int stage) {
        const int kh = tap / 3, kw = tap - kh * 3;
        const int ih = 4 * tile + 2 * ohl + kh;
        const int iw = 2 * owl + kw;
        const u32 a_s = a_row + stage * AST;
        if (ih < 112 && iw < 112) {
            const float* src = g_h1 + img + ((size_t)ih * 112 + iw) * 64 + half * 32;
            #pragma unroll
            for (int j = 0; j < 8; ++j) cp16(a_s + j * 16, src + j * 4);
        } else {
            uint4* p = (uint4*)(smem + stage * AST + m * 288 + half * 128);
            const uint4 z = make_uint4(0, 0, 0, 0);
            #pragma unroll
            for (int j = 0; j < 8; ++j) p[j] = z;
        }
        const u32 b_s = b_row + stage * AST;
        const float* bsrc = wt_base + (size_t)tap * 8192;
        #pragma unroll
        for (int j = 0; j < 8; ++j) cp16(b_s + j * 16, bsrc + j * 4);
    };

    // ---- warp tile setup
    const int warp_m = (wid & 3) * 32;
    const int warp_n = (wid >> 2) * 64;
    const u32 frag_off = (u32)((lane >> 2) * 288 + (lane & 3) * 8);

    float acc[2][8][4];
    #pragma unroll
    for (int i = 0; i < 2; ++i)
        #pragma unroll
        for (int j = 0; j < 8; ++j)
            #pragma unroll
            for (int t = 0; t < 4; ++t) acc[i][j][t] = 0.0f;

    load_tap(0, 0); cp_commit();

    for (int t = 0; t < 9; ++t) {
        const int stage = t & 1;
        if (t < 8) { load_tap(t + 1, stage ^ 1); cp_commit(); cp_wait<1>(); }
        else       { cp_wait<0>(); }
        __syncthreads();

        const u32 abase = sb + stage * AST + warp_m * 288 + frag_off;
        const u32 bbase = sb + SMEM_B0 + stage * AST + warp_n * 288 + frag_off;
        #pragma unroll
        for (int s = 0; s < 8; ++s) {
            u32 A0[2], A1[2], A2[2], A3[2];
            #pragma unroll
            for (int i = 0; i < 2; ++i) {
                lds2(A0[i], A2[i], abase + i * (16 * 288) + s * 32);
                lds2(A1[i], A3[i], abase + i * (16 * 288) + 8 * 288 + s * 32);
            }
            #pragma unroll
            for (int j = 0; j < 8; ++j) {
                u32 B0, B1;
                lds2(B0, B1, bbase + j * (8 * 288) + s * 32);
                #pragma unroll
                for (int i = 0; i < 2; ++i)
                    mma_tf32(acc[i][j], A0[i], A1[i], A2[i], A3[i], B0, B1);
            }
        }
        __syncthreads();
    }

    // ---- epilogue: bias + ReLU + masked pool (ow<56), deterministic
    {
        const int g = lane >> 2, c = lane & 3;
        #pragma unroll
        for (int j = 0; j < 8; ++j) {
            float s0 = 0.0f, s1 = 0.0f;
            const int n0 = warp_n + j * 8 + 2 * c;
            const float bi0 = bias_s[n0], bi1 = bias_s[n0 + 1];
            #pragma unroll
            for (int i = 0; i < 2; ++i) {
                const int rlo = warp_m + i * 16 + g;
                const int rhi = rlo + 8;
                const bool vlo = (rlo & 63) < 56, vhi = (rhi & 63) < 56;
                if (vlo) { s0 += fmaxf(acc[i][j][0] + bi0, 0.0f);
                           s1 += fmaxf(acc[i][j][1] + bi1, 0.0f); }
                if (vhi) { s0 += fmaxf(acc[i][j][2] + bi0, 0.0f);
                           s1 += fmaxf(acc[i][j][3] + bi1, 0.0f); }
            }
            #pragma unroll
            for (int sh = 4; sh < 32; sh <<= 1) {
                s0 += __shfl_down_sync(0xffffffffu, s0, sh);
                s1 += __shfl_down_sync(0xffffffffu, s1, sh);
            }
            if (g == 0) {
                wsum[wid * 128 + n0]     = s0;
                wsum[wid * 128 + n0 + 1] = s1;
            }
        }
    }
    __syncthreads();
    if (tid < 128) {
        const int wbase = (tid < 64) ? 0 : 4;
        float s = 0.0f;
        #pragma unroll
        for (int wq = 0; wq < 4; ++wq) s += wsum[(wbase + wq) * 128 + tid];
        g_partial[(((size_t)e * BATCH + b) * 28 + tile) * 128 + tid] = s;
    }
}

// ---------------------------------------------------------------------------
// head: reduce tile partials -> GAP -> FC -> softmax conf -> blend + freq
// ---------------------------------------------------------------------------
__global__ void head_kernel(const float* __restrict__ t_wf, const float* __restrict__ t_bf,
                            const float* __restrict__ f_wf, const float* __restrict__ f_bf,
                            float* __restrict__ out, int out_size)
{
    __shared__ int cnt;
    const int b = threadIdx.x;   // 0..63
    if (b == 0) cnt = 0;
    __syncthreads();

    const float inv = 1.0f / 3136.0f;
    float tl0 = t_bf[0], tl1 = t_bf[1];
    float fl0 = f_bf[0], fl1 = f_bf[1];
    const size_t tb = (size_t)b * 28 * 128;
    const size_t fb = (size_t)(BATCH + b) * 28 * 128;

    for (int c = 0; c < 128; ++c) {
        float st = 0.0f, sf = 0.0f;
        #pragma unroll
        for (int tt = 0; tt < 28; ++tt) {
            st += g_partial[tb + (size_t)tt * 128 + c];
            sf += g_partial[fb + (size_t)tt * 128 + c];
        }
        const float gt = st * inv;
        const float gf = sf * inv;
        tl0 = fmaf(gt, t_wf[c * 2 + 0], tl0);
        tl1 = fmaf(gt, t_wf[c * 2 + 1], tl1);
        fl0 = fmaf(gf, f_wf[c * 2 + 0], fl0);
        fl1 = fmaf(gf, f_wf[c * 2 + 1], fl1);
    }

    const float mx = fmaxf(tl0, tl1);
    const float e0 = expf(tl0 - mx), e1 = expf(tl1 - mx);
    const float conf = fmaxf(e0, e1) / (e0 + e1);
    const bool use2 = (conf <= 0.9f);

    out[b * 2 + 0] = use2 ? 0.7f * tl0 + 0.3f * fl0 : tl0;
    out[b * 2 + 1] = use2 ? 0.7f * tl1 + 0.3f * fl1 : tl1;

    if (use2) atomicAdd(&cnt, 1);
    __syncthreads();
    if (b == 0 && out_size > 128) out[128] = (float)cnt * (1.0f / 64.0f);
}

// ---------------------------------------------------------------------------
extern "C" void kernel_launch(void* const* d_in, const int* in_sizes, int n_in,
                              void* d_out, int out_size)
{
    const float* x    = (const float*)d_in[0];
    const float* t_w1 = (const float*)d_in[1];
    const float* t_b1 = (const float*)d_in[2];
    const float* t_w2 = (const float*)d_in[3];
    const float* t_b2 = (const float*)d_in[4];
    const float* t_wf = (const float*)d_in[5];
    const float* t_bf = (const float*)d_in[6];
    const float* f_w1 = (const float*)d_in[7];
    const float* f_b1 = (const float*)d_in[8];
    const float* f_w2 = (const float*)d_in[9];
    const float* f_b2 = (const float*)d_in[10];
    const float* f_wf = (const float*)d_in[11];
    const float* f_bf = (const float*)d_in[12];
    float* out = (float*)d_out;

    cudaFuncSetAttribute(conv2_kernel, cudaFuncAttributeMaxDynamicSharedMemorySize, SMEM_TOTAL);

    prep_w2<<<576, 256>>>(t_w2, f_w2);
    conv1_kernel<<<dim3(49, BATCH, 2), 256>>>(x, t_w1, t_b1, f_w1, f_b1);
    conv2_kernel<<<dim3(28, BATCH, 2), 256, SMEM_TOTAL>>>(t_b2, f_b2);
    head_kernel<<<1, 64>>>(t_wf, t_bf, f_wf, f_bf, out, out_size);
}

// round 6
// speedup vs baseline: 2.6456x; 1.3085x over previous
#include <cuda_runtime.h>
#include <cstdint>

#define BATCH 64
typedef unsigned long long ull;
typedef uint32_t u32;

// ---------------------------------------------------------------------------
// Device scratch
// ---------------------------------------------------------------------------
__device__ float g_h1[2ULL * BATCH * 112 * 112 * 64];   // NHWC (ic-permuted, tf32-rounded)
__device__ float g_w2t[2 * 9 * 128 * 64];               // [e][tap][oc][ic-permuted], tf32
__device__ float g_partial[2 * BATCH * 28 * 128];       // pooled partials per M-tile
__device__ float g_flags[BATCH];                        // per-batch use2 flag

// ---------------------------------------------------------------------------
// helpers
// ---------------------------------------------------------------------------
__device__ __forceinline__ ull pack2(float lo, float hi) {
    ull r; asm("mov.b64 %0, {%1,%2};" : "=l"(r) : "f"(lo), "f"(hi)); return r;
}
__device__ __forceinline__ void unpack2(ull v, float& lo, float& hi) {
    asm("mov.b64 {%0,%1}, %2;" : "=f"(lo), "=f"(hi) : "l"(v));
}
__device__ __forceinline__ ull fma2(ull a, ull b, ull c) {
    ull d; asm("fma.rn.f32x2 %0, %1, %2, %3;" : "=l"(d) : "l"(a), "l"(b), "l"(c)); return d;
}
__device__ __forceinline__ float to_tf32(float f) {
    u32 r; asm("cvt.rna.tf32.f32 %0, %1;" : "=r"(r) : "f"(f));
    return __uint_as_float(r);
}
__device__ __forceinline__ u32 smem_u32(const void* p) {
    return (u32)__cvta_generic_to_shared(p);
}
__device__ __forceinline__ void cp16(u32 dst, const void* src) {
    asm volatile("cp.async.cg.shared.global [%0], [%1], 16;" :: "r"(dst), "l"(src));
}
__device__ __forceinline__ void cp_commit() {
    asm volatile("cp.async.commit_group;" ::: "memory");
}
template<int N> __device__ __forceinline__ void cp_wait() {
    asm volatile("cp.async.wait_group %0;" :: "n"(N) : "memory");
}
__device__ __forceinline__ void lds2(u32& x, u32& y, u32 addr) {
    asm volatile("ld.shared.v2.b32 {%0,%1}, [%2];" : "=r"(x), "=r"(y) : "r"(addr));
}
__device__ __forceinline__ void mma_tf32(float* c, u32 a0, u32 a1, u32 a2, u32 a3,
                                         u32 b0, u32 b1) {
    asm volatile(
        "mma.sync.aligned.m16n8k8.row.col.f32.tf32.tf32.f32 "
        "{%0,%1,%2,%3}, {%4,%5,%6,%7}, {%8,%9}, {%0,%1,%2,%3};"
        : "+f"(c[0]), "+f"(c[1]), "+f"(c[2]), "+f"(c[3])
        : "r"(a0), "r"(a1), "r"(a2), "r"(a3), "r"(b0), "r"(b1));
}

// ic permutation so mma's (k, k+4) fragment pair is one 64-bit shared load
__device__ __forceinline__ int perm_src(int p) {
    return (p & ~7) | (((p & 7) >> 1) + ((p & 1) << 2));
}

// ---------------------------------------------------------------------------
// prep: transpose conv2 weights [oc][ic][kh][kw] -> [e][tap][oc][icp] (tf32)
// ---------------------------------------------------------------------------
__global__ void prep_w2(const float* __restrict__ tw2, const float* __restrict__ fw2)
{
    const int i = blockIdx.x * 256 + threadIdx.x;   // < 147456
    const int e = i / 73728;
    const int r = i - e * 73728;
    const int tap = r / 8192;
    const int r2 = r - tap * 8192;
    const int oc = r2 >> 6, icp = r2 & 63;
    const int ic = perm_src(icp);
    const float* w = e ? fw2 : tw2;
    g_w2t[i] = to_tf32(w[oc * 576 + ic * 9 + tap]);
}

// ---------------------------------------------------------------------------
// conv1 + ReLU (f32x2) -> NHWC permuted tf32, smem-staged coalesced stores.
// grid=(49, BATCH, 2), 256 threads, dyn smem 256*68*4 = 69632 B
// ---------------------------------------------------------------------------
#define C1_SMEM (256 * 68 * 4)

__global__ __launch_bounds__(256) void conv1_kernel(const float* __restrict__ x,
                                                    const float* __restrict__ wt,
                                                    const float* __restrict__ bt,
                                                    const float* __restrict__ wf,
                                                    const float* __restrict__ bf)
{
    __shared__ float ws[27 * 64];   // [k 27][oc 64]
    __shared__ float bs[64];
    extern __shared__ float so[];   // [256 pos][68]
    const int tid = threadIdx.x;
    const int b = blockIdx.y, e = blockIdx.z;
    const float* w = e ? wf : wt;
    const float* bias = e ? bf : bt;

    for (int i = tid; i < 27 * 64; i += 256) {
        int oc = i / 27, k = i % 27;
        ws[k * 64 + oc] = w[i];
    }
    if (tid < 64) bs[tid] = bias[tid];
    __syncthreads();

    const int pos = blockIdx.x * 256 + tid;    // 0..12543
    const int oh = pos / 112, ow = pos % 112;
    const int ih0 = oh * 2, iw0 = ow * 2;
    const bool bh = (oh < 111), bw = (ow < 111);

    ull pin[27];
    const float* xb = x + (size_t)b * (3 * 224 * 224);
    #pragma unroll
    for (int ic = 0; ic < 3; ++ic) {
        const float* p = xb + ic * (224 * 224) + ih0 * 224 + iw0;
        #pragma unroll
        for (int kh = 0; kh < 3; ++kh) {
            #pragma unroll
            for (int kw = 0; kw < 3; ++kw) {
                bool ok = (kh < 2 || bh) && (kw < 2 || bw);
                float v = ok ? p[kh * 224 + kw] : 0.0f;
                pin[ic * 9 + kh * 3 + kw] = pack2(v, v);
            }
        }
    }

    #pragma unroll
    for (int occ = 0; occ < 4; ++occ) {
        ull acc[8];
        #pragma unroll
        for (int j = 0; j < 8; ++j)
            acc[j] = pack2(bs[occ * 16 + 2 * j], bs[occ * 16 + 2 * j + 1]);
        #pragma unroll
        for (int k = 0; k < 27; ++k) {
            const ull* w2 = (const ull*)(ws + k * 64 + occ * 16);
            #pragma unroll
            for (int j = 0; j < 8; ++j)
                acc[j] = fma2(pin[k], w2[j], acc[j]);
        }
        float ov[16];
        #pragma unroll
        for (int j = 0; j < 8; ++j) {
            float lo, hi; unpack2(acc[j], lo, hi);
            ov[2 * j]     = fmaxf(lo, 0.0f);
            ov[2 * j + 1] = fmaxf(hi, 0.0f);
        }
        // permuted tf32 into staging smem (STS.128, min-phase)
        #pragma unroll
        for (int q = 0; q < 4; ++q) {
            float4 v = make_float4(to_tf32(ov[perm_src(4 * q + 0)]),
                                   to_tf32(ov[perm_src(4 * q + 1)]),
                                   to_tf32(ov[perm_src(4 * q + 2)]),
                                   to_tf32(ov[perm_src(4 * q + 3)]));
            *(float4*)(so + tid * 68 + occ * 16 + 4 * q) = v;
        }
    }
    __syncthreads();

    // fully-coalesced linear stores: block covers one contiguous 64 KB span
    float4* out4 = (float4*)(g_h1 + ((size_t)(e * BATCH + b) * 12544
                                     + (size_t)blockIdx.x * 256) * 64);
    #pragma unroll
    for (int k = 0; k < 16; ++k) {
        const int f = k * 256 + tid;          // float4 index 0..4095
        const int lpos = f >> 4, c4 = (f & 15) * 4;
        out4[f] = *(const float4*)(so + lpos * 68 + c4);
    }
}

// ---------------------------------------------------------------------------
// conv2: implicit GEMM on mma.sync tf32 + fused bias/ReLU/GAP epilogue.
// Tile M=128 (2 oh x 64 ow; ow>=56 padded), N=128 oc, K=9 taps x 64 ic.
// ---------------------------------------------------------------------------
#define AST       36864
#define SMEM_B0   73728
#define SMEM_MISC 147456
#define SMEM_TOTAL (147456 + 512 + 4096)

__global__ __launch_bounds__(256, 1) void conv2_kernel(const float* __restrict__ bias_t,
                                                       const float* __restrict__ bias_f)
{
    extern __shared__ __align__(256) char smem[];
    const int tid = threadIdx.x;
    const int wid = tid >> 5, lane = tid & 31;
    const int tile = blockIdx.x, b = blockIdx.y, e = blockIdx.z;
    const u32 sb = smem_u32(smem);

    float* bias_s = (float*)(smem + SMEM_MISC);
    float* wsum   = (float*)(smem + SMEM_MISC + 512);   // [8 warps][128]

    if (tid < 128) bias_s[tid] = (e ? bias_f : bias_t)[tid];

    const int m = tid >> 1;
    const int half = tid & 1;
    const int ohl = m >> 6, owl = m & 63;
    const size_t img = (size_t)(e * BATCH + b) * (112 * 112 * 64);
    const float* wt_base = g_w2t + (size_t)e * (9 * 128 * 64) + (size_t)m * 64 + half * 32;
    const u32 a_row = sb + m * 288 + half * 128;
    const u32 b_row = sb + SMEM_B0 + m * 288 + half * 128;

    auto load_tap = [&](int tap, int stage) {
        const int kh = tap / 3, kw = tap - kh * 3;
        const int ih = 4 * tile + 2 * ohl + kh;
        const int iw = 2 * owl + kw;
        const u32 a_s = a_row + stage * AST;
        if (ih < 112 && iw < 112) {
            const float* src = g_h1 + img + ((size_t)ih * 112 + iw) * 64 + half * 32;
            #pragma unroll
            for (int j = 0; j < 8; ++j) cp16(a_s + j * 16, src + j * 4);
        } else {
            uint4* p = (uint4*)(smem + stage * AST + m * 288 + half * 128);
            const uint4 z = make_uint4(0, 0, 0, 0);
            #pragma unroll
            for (int j = 0; j < 8; ++j) p[j] = z;
        }
        const u32 b_s = b_row + stage * AST;
        const float* bsrc = wt_base + (size_t)tap * 8192;
        #pragma unroll
        for (int j = 0; j < 8; ++j) cp16(b_s + j * 16, bsrc + j * 4);
    };

    const int warp_m = (wid & 3) * 32;
    const int warp_n = (wid >> 2) * 64;
    const u32 frag_off = (u32)((lane >> 2) * 288 + (lane & 3) * 8);

    float acc[2][8][4];
    #pragma unroll
    for (int i = 0; i < 2; ++i)
        #pragma unroll
        for (int j = 0; j < 8; ++j)
            #pragma unroll
            for (int t = 0; t < 4; ++t) acc[i][j][t] = 0.0f;

    load_tap(0, 0); cp_commit();

    for (int t = 0; t < 9; ++t) {
        const int stage = t & 1;
        if (t < 8) { load_tap(t + 1, stage ^ 1); cp_commit(); cp_wait<1>(); }
        else       { cp_wait<0>(); }
        __syncthreads();

        const u32 abase = sb + stage * AST + warp_m * 288 + frag_off;
        const u32 bbase = sb + SMEM_B0 + stage * AST + warp_n * 288 + frag_off;
        #pragma unroll
        for (int s = 0; s < 8; ++s) {
            u32 A0[2], A1[2], A2[2], A3[2];
            #pragma unroll
            for (int i = 0; i < 2; ++i) {
                lds2(A0[i], A2[i], abase + i * (16 * 288) + s * 32);
                lds2(A1[i], A3[i], abase + i * (16 * 288) + 8 * 288 + s * 32);
            }
            #pragma unroll
            for (int j = 0; j < 8; ++j) {
                u32 B0, B1;
                lds2(B0, B1, bbase + j * (8 * 288) + s * 32);
                #pragma unroll
                for (int i = 0; i < 2; ++i)
                    mma_tf32(acc[i][j], A0[i], A1[i], A2[i], A3[i], B0, B1);
            }
        }
        __syncthreads();
    }

    {
        const int g = lane >> 2, c = lane & 3;
        #pragma unroll
        for (int j = 0; j < 8; ++j) {
            float s0 = 0.0f, s1 = 0.0f;
            const int n0 = warp_n + j * 8 + 2 * c;
            const float bi0 = bias_s[n0], bi1 = bias_s[n0 + 1];
            #pragma unroll
            for (int i = 0; i < 2; ++i) {
                const int rlo = warp_m + i * 16 + g;
                const int rhi = rlo + 8;
                const bool vlo = (rlo & 63) < 56, vhi = (rhi & 63) < 56;
                if (vlo) { s0 += fmaxf(acc[i][j][0] + bi0, 0.0f);
                           s1 += fmaxf(acc[i][j][1] + bi1, 0.0f); }
                if (vhi) { s0 += fmaxf(acc[i][j][2] + bi0, 0.0f);
                           s1 += fmaxf(acc[i][j][3] + bi1, 0.0f); }
            }
            #pragma unroll
            for (int sh = 4; sh < 32; sh <<= 1) {
                s0 += __shfl_down_sync(0xffffffffu, s0, sh);
                s1 += __shfl_down_sync(0xffffffffu, s1, sh);
            }
            if (g == 0) {
                wsum[wid * 128 + n0]     = s0;
                wsum[wid * 128 + n0 + 1] = s1;
            }
        }
    }
    __syncthreads();
    if (tid < 128) {
        const int wbase = (tid < 64) ? 0 : 4;
        float s = 0.0f;
        #pragma unroll
        for (int wq = 0; wq < 4; ++wq) s += wsum[(wbase + wq) * 128 + tid];
        g_partial[(((size_t)e * BATCH + b) * 28 + tile) * 128 + tid] = s;
    }
}

// ---------------------------------------------------------------------------
// head: grid=64 blocks (one per batch) x 128 threads (one per channel)
// ---------------------------------------------------------------------------
__global__ void head_kernel(const float* __restrict__ t_wf, const float* __restrict__ t_bf,
                            const float* __restrict__ f_wf, const float* __restrict__ f_bf,
                            float* __restrict__ out)
{
    __shared__ float red[16];      // [4 warps][4 sums]
    const int b = blockIdx.x;
    const int c = threadIdx.x;     // channel 0..127
    const int lane = c & 31, warp = c >> 5;

    const float inv = 1.0f / 3136.0f;
    const size_t tb = (size_t)b * 28 * 128 + c;
    const size_t fb = (size_t)(BATCH + b) * 28 * 128 + c;

    float st = 0.0f, sf = 0.0f;
    #pragma unroll
    for (int tt = 0; tt < 28; ++tt) {
        st += g_partial[tb + (size_t)tt * 128];
        sf += g_partial[fb + (size_t)tt * 128];
    }
    const float gt = st * inv, gf = sf * inv;
    float p0 = gt * t_wf[c * 2 + 0];
    float p1 = gt * t_wf[c * 2 + 1];
    float p2 = gf * f_wf[c * 2 + 0];
    float p3 = gf * f_wf[c * 2 + 1];

    #pragma unroll
    for (int sh = 16; sh > 0; sh >>= 1) {
        p0 += __shfl_down_sync(0xffffffffu, p0, sh);
        p1 += __shfl_down_sync(0xffffffffu, p1, sh);
        p2 += __shfl_down_sync(0xffffffffu, p2, sh);
        p3 += __shfl_down_sync(0xffffffffu, p3, sh);
    }
    if (lane == 0) {
        red[warp * 4 + 0] = p0; red[warp * 4 + 1] = p1;
        red[warp * 4 + 2] = p2; red[warp * 4 + 3] = p3;
    }
    __syncthreads();
    if (c == 0) {
        float tl0 = t_bf[0], tl1 = t_bf[1], fl0 = f_bf[0], fl1 = f_bf[1];
        #pragma unroll
        for (int wq = 0; wq < 4; ++wq) {
            tl0 += red[wq * 4 + 0]; tl1 += red[wq * 4 + 1];
            fl0 += red[wq * 4 + 2]; fl1 += red[wq * 4 + 3];
        }
        const float mx = fmaxf(tl0, tl1);
        const float e0 = expf(tl0 - mx), e1 = expf(tl1 - mx);
        const float conf = fmaxf(e0, e1) / (e0 + e1);
        const bool use2 = (conf <= 0.9f);
        out[b * 2 + 0] = use2 ? 0.7f * tl0 + 0.3f * fl0 : tl0;
        out[b * 2 + 1] = use2 ? 0.7f * tl1 + 0.3f * fl1 : tl1;
        g_flags[b] = use2 ? 1.0f : 0.0f;
    }
}

__global__ void head2_kernel(float* __restrict__ out, int out_size)
{
    __shared__ float s[64];
    const int t = threadIdx.x;
    s[t] = g_flags[t];
    __syncthreads();
    if (t == 0) {
        float acc = 0.0f;
        #pragma unroll
        for (int i = 0; i < 64; ++i) acc += s[i];
        if (out_size > 128) out[128] = acc * (1.0f / 64.0f);
    }
}

// ---------------------------------------------------------------------------
extern "C" void kernel_launch(void* const* d_in, const int* in_sizes, int n_in,
                              void* d_out, int out_size)
{
    const float* x    = (const float*)d_in[0];
    const float* t_w1 = (const float*)d_in[1];
    const float* t_b1 = (const float*)d_in[2];
    const float* t_w2 = (const float*)d_in[3];
    const float* t_b2 = (const float*)d_in[4];
    const float* t_wf = (const float*)d_in[5];
    const float* t_bf = (const float*)d_in[6];
    const float* f_w1 = (const float*)d_in[7];
    const float* f_b1 = (const float*)d_in[8];
    const float* f_w2 = (const float*)d_in[9];
    const float* f_b2 = (const float*)d_in[10];
    const float* f_wf = (const float*)d_in[11];
    const float* f_bf = (const float*)d_in[12];
    float* out = (float*)d_out;

    cudaFuncSetAttribute(conv1_kernel, cudaFuncAttributeMaxDynamicSharedMemorySize, C1_SMEM);
    cudaFuncSetAttribute(conv2_kernel, cudaFuncAttributeMaxDynamicSharedMemorySize, SMEM_TOTAL);

    prep_w2<<<576, 256>>>(t_w2, f_w2);
    conv1_kernel<<<dim3(49, BATCH, 2), 256, C1_SMEM>>>(x, t_w1, t_b1, f_w1, f_b1);
    conv2_kernel<<<dim3(28, BATCH, 2), 256, SMEM_TOTAL>>>(t_b2, f_b2);
    head_kernel<<<64, 128>>>(t_wf, t_bf, f_wf, f_bf, out);
    head2_kernel<<<1, 64>>>(out, out_size);
}

// round 10
// speedup vs baseline: 5.1584x; 1.9498x over previous
#include <cuda_runtime.h>
#include <cuda_fp16.h>
#include <cstdint>

#define BATCH 64
typedef unsigned long long ull;
typedef uint32_t u32;

// ---------------------------------------------------------------------------
// Device scratch
// ---------------------------------------------------------------------------
__device__ __half g_h1h[2ULL * BATCH * 112 * 112 * 64]; // NHWC fp16, k-chunk permuted
__device__ __half g_w2h[2 * 9 * 128 * 64];              // [e][tap][oc][icp] fp16
__device__ float  g_partial[2 * BATCH * 28 * 128];      // pooled partials per M-tile
__device__ float  g_flags[BATCH];                       // per-batch use2 flag

// ---------------------------------------------------------------------------
// helpers
// ---------------------------------------------------------------------------
__device__ __forceinline__ ull pack2(float lo, float hi) {
    ull r; asm("mov.b64 %0, {%1,%2};" : "=l"(r) : "f"(lo), "f"(hi)); return r;
}
__device__ __forceinline__ void unpack2(ull v, float& lo, float& hi) {
    asm("mov.b64 {%0,%1}, %2;" : "=f"(lo), "=f"(hi) : "l"(v));
}
__device__ __forceinline__ ull fma2(ull a, ull b, ull c) {
    ull d; asm("fma.rn.f32x2 %0, %1, %2, %3;" : "=l"(d) : "l"(a), "l"(b), "l"(c)); return d;
}
__device__ __forceinline__ u32 smem_u32(const void* p) {
    return (u32)__cvta_generic_to_shared(p);
}
__device__ __forceinline__ void cp16(u32 dst, const void* src) {
    asm volatile("cp.async.cg.shared.global [%0], [%1], 16;" :: "r"(dst), "l"(src));
}
__device__ __forceinline__ void cp_commit() {
    asm volatile("cp.async.commit_group;" ::: "memory");
}
template<int N> __device__ __forceinline__ void cp_wait() {
    asm volatile("cp.async.wait_group %0;" :: "n"(N) : "memory");
}
__device__ __forceinline__ void lds2(u32& x, u32& y, u32 addr) {
    asm volatile("ld.shared.v2.b32 {%0,%1}, [%2];" : "=r"(x), "=r"(y) : "r"(addr));
}
// fp16 mma m16n8k16, fp32 accumulate. A regs order: {row,k0},{row+8,k0},{row,k8},{row+8,k8}
__device__ __forceinline__ void mma_f16(float* c, u32 a0, u32 a1, u32 a2, u32 a3,
                                        u32 b0, u32 b1) {
    asm volatile(
        "mma.sync.aligned.m16n8k16.row.col.f32.f16.f16.f32 "
        "{%0,%1,%2,%3}, {%4,%5,%6,%7}, {%8,%9}, {%0,%1,%2,%3};"
        : "+f"(c[0]), "+f"(c[1]), "+f"(c[2]), "+f"(c[3])
        : "r"(a0), "r"(a1), "r"(a2), "r"(a3), "r"(b0), "r"(b1));
}

// k-chunk permutation: within each 16-half group, stored 2-half chunk q holds
// original chunk c = (q>>1) | ((q&1)<<2), so frag pairs (c, c+4) are adjacent.
// stored half p -> original half:
__device__ __forceinline__ int perm16(int p) {
    int g = p & ~15, h = p & 15, q = h >> 1, bb = h & 1;
    int c = (q >> 1) | ((q & 1) << 2);
    return g | (c << 1) | bb;
}

// ---------------------------------------------------------------------------
// prep: conv2 weights [oc][ic][3][3] -> [e][tap][oc][icp] fp16
// ---------------------------------------------------------------------------
__global__ void prep_w2(const float* __restrict__ tw2, const float* __restrict__ fw2)
{
    const int i = blockIdx.x * 256 + threadIdx.x;   // < 147456
    const int e = i / 73728;
    const int r = i - e * 73728;
    const int tap = r / 8192;
    const int r2 = r - tap * 8192;
    const int oc = r2 >> 6, icp = r2 & 63;
    const int ic = perm16(icp);
    const float* w = e ? fw2 : tw2;
    g_w2h[i] = __float2half(w[oc * 576 + ic * 9 + tap]);
}

// ---------------------------------------------------------------------------
// conv1 + ReLU (f32x2) -> NHWC permuted fp16, smem-staged coalesced stores.
// grid=(49, BATCH, 2), 256 threads, dyn smem 256*36*4 = 36864 B
// ---------------------------------------------------------------------------
#define C1_SMEM (256 * 36 * 4)

__global__ __launch_bounds__(256) void conv1_kernel(const float* __restrict__ x,
                                                    const float* __restrict__ wt,
                                                    const float* __restrict__ bt,
                                                    const float* __restrict__ wf,
                                                    const float* __restrict__ bf)
{
    __shared__ float ws[27 * 64];   // [k 27][oc 64]
    __shared__ float bs[64];
    extern __shared__ u32 so[];     // [256 pos][36 u32] (32 data + 4 pad)
    const int tid = threadIdx.x;
    const int b = blockIdx.y, e = blockIdx.z;
    const float* w = e ? wf : wt;
    const float* bias = e ? bf : bt;

    for (int i = tid; i < 27 * 64; i += 256) {
        int oc = i / 27, k = i % 27;
        ws[k * 64 + oc] = w[i];
    }
    if (tid < 64) bs[tid] = bias[tid];
    __syncthreads();

    const int pos = blockIdx.x * 256 + tid;    // 0..12543
    const int oh = pos / 112, ow = pos % 112;
    const int ih0 = oh * 2, iw0 = ow * 2;
    const bool bh = (oh < 111), bw = (ow < 111);

    ull pin[27];
    const float* xb = x + (size_t)b * (3 * 224 * 224);
    #pragma unroll
    for (int ic = 0; ic < 3; ++ic) {
        const float* p = xb + ic * (224 * 224) + ih0 * 224 + iw0;
        #pragma unroll
        for (int kh = 0; kh < 3; ++kh) {
            #pragma unroll
            for (int kw = 0; kw < 3; ++kw) {
                bool ok = (kh < 2 || bh) && (kw < 2 || bw);
                float v = ok ? p[kh * 224 + kw] : 0.0f;
                pin[ic * 9 + kh * 3 + kw] = pack2(v, v);
            }
        }
    }

    float ov[64];
    #pragma unroll
    for (int occ = 0; occ < 4; ++occ) {
        ull acc[8];
        #pragma unroll
        for (int j = 0; j < 8; ++j)
            acc[j] = pack2(bs[occ * 16 + 2 * j], bs[occ * 16 + 2 * j + 1]);
        #pragma unroll
        for (int k = 0; k < 27; ++k) {
            const ull* w2 = (const ull*)(ws + k * 64 + occ * 16);
            #pragma unroll
            for (int j = 0; j < 8; ++j)
                acc[j] = fma2(pin[k], w2[j], acc[j]);
        }
        #pragma unroll
        for (int j = 0; j < 8; ++j) {
            float lo, hi; unpack2(acc[j], lo, hi);
            ov[occ * 16 + 2 * j]     = fmaxf(lo, 0.0f);
            ov[occ * 16 + 2 * j + 1] = fmaxf(hi, 0.0f);
        }
    }
    // pack to permuted fp16: stored u32 chunk i holds orig halves (o0, o0+1)
    #pragma unroll
    for (int i = 0; i < 32; ++i) {
        const int g = i >> 3, q = i & 7;
        const int c = (q >> 1) | ((q & 1) << 2);
        const int o0 = g * 16 + c * 2;
        half2 h2 = __floats2half2_rn(ov[o0], ov[o0 + 1]);
        so[tid * 36 + i] = *(u32*)&h2;
    }
    __syncthreads();

    // coalesced: block's 256 pos x 64 halves = 32KB contiguous span
    uint4* out4 = (uint4*)(g_h1h + ((size_t)(e * BATCH + b) * 12544
                                    + (size_t)blockIdx.x * 256) * 64);
    #pragma unroll
    for (int k = 0; k < 8; ++k) {
        const int f = k * 256 + tid;          // uint4 index 0..2047
        const int lpos = f >> 3, c4 = (f & 7) * 4;
        out4[f] = *(const uint4*)(so + lpos * 36 + c4);
    }
}

// ---------------------------------------------------------------------------
// conv2: implicit GEMM, fp16 mma.sync m16n8k16 + fused bias/ReLU/GAP.
// Tile M=128 (2 oh x 64 ow; ow>=56 padded), N=128 oc, K=9 taps x 64 ic.
// 8 warps, warp tile 32x64. grid=(28, BATCH, 2), 256 thr, 2 CTAs/SM.
// SMEM rows: 64 halves (128B) at 160B stride -> conflict-free v2 frag loads.
// ---------------------------------------------------------------------------
#define ROWB  160
#define AST2  (128 * ROWB)          // 20480 per stage
#define B_OFF (2 * AST2)            // 40960
#define MISC  (4 * AST2)            // 81920
#define SMEM_TOTAL2 (MISC + 512 + 4096)

__global__ __launch_bounds__(256, 2) void conv2_kernel(const float* __restrict__ bias_t,
                                                       const float* __restrict__ bias_f)
{
    extern __shared__ __align__(256) char smem[];
    const int tid = threadIdx.x;
    const int wid = tid >> 5, lane = tid & 31;
    const int tile = blockIdx.x, b = blockIdx.y, e = blockIdx.z;
    const u32 sb = smem_u32(smem);

    float* bias_s = (float*)(smem + MISC);
    float* wsum   = (float*)(smem + MISC + 512);   // [8 warps][128]

    if (tid < 128) bias_s[tid] = (e ? bias_f : bias_t)[tid];

    // loader: 2 threads per row, 64B (4 cp16) each
    const int m = tid >> 1;
    const int half = tid & 1;
    const int ohl = m >> 6, owl = m & 63;
    const size_t img = (size_t)(e * BATCH + b) * (112 * 112 * 64);
    const __half* wt_base = g_w2h + (size_t)e * (9 * 128 * 64) + (size_t)m * 64 + half * 32;
    const u32 a_row = sb + m * ROWB + half * 64;
    const u32 b_row = sb + B_OFF + m * ROWB + half * 64;

    auto load_tap = [&](int tap, int stage) {
        const int kh = tap / 3, kw = tap - kh * 3;
        const int ih = 4 * tile + 2 * ohl + kh;
        const int iw = 2 * owl + kw;
        const u32 a_s = a_row + stage * AST2;
        if (ih < 112 && iw < 112) {
            const __half* src = g_h1h + img + ((size_t)ih * 112 + iw) * 64 + half * 32;
            #pragma unroll
            for (int j = 0; j < 4; ++j) cp16(a_s + j * 16, src + j * 8);
        } else {
            uint4* p = (uint4*)(smem + stage * AST2 + m * ROWB + half * 64);
            const uint4 z = make_uint4(0, 0, 0, 0);
            #pragma unroll
            for (int j = 0; j < 4; ++j) p[j] = z;
        }
        const u32 b_s = b_row + stage * AST2;
        const __half* bsrc = wt_base + (size_t)tap * 8192;
        #pragma unroll
        for (int j = 0; j < 4; ++j) cp16(b_s + j * 16, bsrc + j * 8);
    };

    const int warp_m = (wid & 3) * 32;
    const int warp_n = (wid >> 2) * 64;
    const u32 frag_off = (u32)((lane >> 2) * ROWB + (lane & 3) * 8);

    float acc[2][8][4];
    #pragma unroll
    for (int i = 0; i < 2; ++i)
        #pragma unroll
        for (int j = 0; j < 8; ++j)
            #pragma unroll
            for (int t = 0; t < 4; ++t) acc[i][j][t] = 0.0f;

    load_tap(0, 0); cp_commit();

    for (int t = 0; t < 9; ++t) {
        const int stage = t & 1;
        if (t < 8) { load_tap(t + 1, stage ^ 1); cp_commit(); cp_wait<1>(); }
        else       { cp_wait<0>(); }
        __syncthreads();

        const u32 abase = sb + stage * AST2 + warp_m * ROWB + frag_off;
        const u32 bbase = sb + B_OFF + stage * AST2 + warp_n * ROWB + frag_off;
        #pragma unroll
        for (int s = 0; s < 4; ++s) {          // 4 x k16 per tap
            u32 X0[2], X1[2], Y0[2], Y1[2];    // {row,k0} {row+8,k0} {row,k8} {row+8,k8}
            #pragma unroll
            for (int i = 0; i < 2; ++i) {
                lds2(X0[i], Y0[i], abase + i * (16 * ROWB) + s * 32);
                lds2(X1[i], Y1[i], abase + i * (16 * ROWB) + 8 * ROWB + s * 32);
            }
            #pragma unroll
            for (int j = 0; j < 8; ++j) {
                u32 B0, B1;
                lds2(B0, B1, bbase + j * (8 * ROWB) + s * 32);
                #pragma unroll
                for (int i = 0; i < 2; ++i)
                    mma_f16(acc[i][j], X0[i], X1[i], Y0[i], Y1[i], B0, B1);
            }
        }
        __syncthreads();
    }

    // epilogue: bias + ReLU + masked pool (ow<56), deterministic
    {
        const int g = lane >> 2, c = lane & 3;
        #pragma unroll
        for (int j = 0; j < 8; ++j) {
            float s0 = 0.0f, s1 = 0.0f;
            const int n0 = warp_n + j * 8 + 2 * c;
            const float bi0 = bias_s[n0], bi1 = bias_s[n0 + 1];
            #pragma unroll
            for (int i = 0; i < 2; ++i) {
                const int rlo = warp_m + i * 16 + g;
                const int rhi = rlo + 8;
                const bool vlo = (rlo & 63) < 56, vhi = (rhi & 63) < 56;
                if (vlo) { s0 += fmaxf(acc[i][j][0] + bi0, 0.0f);
                           s1 += fmaxf(acc[i][j][1] + bi1, 0.0f); }
                if (vhi) { s0 += fmaxf(acc[i][j][2] + bi0, 0.0f);
                           s1 += fmaxf(acc[i][j][3] + bi1, 0.0f); }
            }
            #pragma unroll
            for (int sh = 4; sh < 32; sh <<= 1) {
                s0 += __shfl_down_sync(0xffffffffu, s0, sh);
                s1 += __shfl_down_sync(0xffffffffu, s1, sh);
            }
            if (g == 0) {
                wsum[wid * 128 + n0]     = s0;
                wsum[wid * 128 + n0 + 1] = s1;
            }
        }
    }
    __syncthreads();
    if (tid < 128) {
        const int wbase = (tid < 64) ? 0 : 4;
        float s = 0.0f;
        #pragma unroll
        for (int wq = 0; wq < 4; ++wq) s += wsum[(wbase + wq) * 128 + tid];
        g_partial[(((size_t)e * BATCH + b) * 28 + tile) * 128 + tid] = s;
    }
}

// ---------------------------------------------------------------------------
// head: grid=64 blocks (one per batch) x 128 threads (one per channel)
// ---------------------------------------------------------------------------
__global__ void head_kernel(const float* __restrict__ t_wf, const float* __restrict__ t_bf,
                            const float* __restrict__ f_wf, const float* __restrict__ f_bf,
                            float* __restrict__ out)
{
    __shared__ float red[16];
    const int b = blockIdx.x;
    const int c = threadIdx.x;
    const int lane = c & 31, warp = c >> 5;

    const float inv = 1.0f / 3136.0f;
    const size_t tb = (size_t)b * 28 * 128 + c;
    const size_t fb = (size_t)(BATCH + b) * 28 * 128 + c;

    float st = 0.0f, sf = 0.0f;
    #pragma unroll
    for (int tt = 0; tt < 28; ++tt) {
        st += g_partial[tb + (size_t)tt * 128];
        sf += g_partial[fb + (size_t)tt * 128];
    }
    const float gt = st * inv, gf = sf * inv;
    float p0 = gt * t_wf[c * 2 + 0];
    float p1 = gt * t_wf[c * 2 + 1];
    float p2 = gf * f_wf[c * 2 + 0];
    float p3 = gf * f_wf[c * 2 + 1];

    #pragma unroll
    for (int sh = 16; sh > 0; sh >>= 1) {
        p0 += __shfl_down_sync(0xffffffffu, p0, sh);
        p1 += __shfl_down_sync(0xffffffffu, p1, sh);
        p2 += __shfl_down_sync(0xffffffffu, p2, sh);
        p3 += __shfl_down_sync(0xffffffffu, p3, sh);
    }
    if (lane == 0) {
        red[warp * 4 + 0] = p0; red[warp * 4 + 1] = p1;
        red[warp * 4 + 2] = p2; red[warp * 4 + 3] = p3;
    }
    __syncthreads();
    if (c == 0) {
        float tl0 = t_bf[0], tl1 = t_bf[1], fl0 = f_bf[0], fl1 = f_bf[1];
        #pragma unroll
        for (int wq = 0; wq < 4; ++wq) {
            tl0 += red[wq * 4 + 0]; tl1 += red[wq * 4 + 1];
            fl0 += red[wq * 4 + 2]; fl1 += red[wq * 4 + 3];
        }
        const float mx = fmaxf(tl0, tl1);
        const float e0 = expf(tl0 - mx), e1 = expf(tl1 - mx);
        const float conf = fmaxf(e0, e1) / (e0 + e1);
        const bool use2 = (conf <= 0.9f);
        out[b * 2 + 0] = use2 ? 0.7f * tl0 + 0.3f * fl0 : tl0;
        out[b * 2 + 1] = use2 ? 0.7f * tl1 + 0.3f * fl1 : tl1;
        g_flags[b] = use2 ? 1.0f : 0.0f;
    }
}

__global__ void head2_kernel(float* __restrict__ out, int out_size)
{
    __shared__ float s[64];
    const int t = threadIdx.x;
    s[t] = g_flags[t];
    __syncthreads();
    if (t == 0) {
        float acc = 0.0f;
        #pragma unroll
        for (int i = 0; i < 64; ++i) acc += s[i];
        if (out_size > 128) out[128] = acc * (1.0f / 64.0f);
    }
}

// ---------------------------------------------------------------------------
extern "C" void kernel_launch(void* const* d_in, const int* in_sizes, int n_in,
                              void* d_out, int out_size)
{
    const float* x    = (const float*)d_in[0];
    const float* t_w1 = (const float*)d_in[1];
    const float* t_b1 = (const float*)d_in[2];
    const float* t_w2 = (const float*)d_in[3];
    const float* t_b2 = (const float*)d_in[4];
    const float* t_wf = (const float*)d_in[5];
    const float* t_bf = (const float*)d_in[6];
    const float* f_w1 = (const float*)d_in[7];
    const float* f_b1 = (const float*)d_in[8];
    const float* f_w2 = (const float*)d_in[9];
    const float* f_b2 = (const float*)d_in[10];
    const float* f_wf = (const float*)d_in[11];
    const float* f_bf = (const float*)d_in[12];
    float* out = (float*)d_out;

    cudaFuncSetAttribute(conv1_kernel, cudaFuncAttributeMaxDynamicSharedMemorySize, C1_SMEM);
    cudaFuncSetAttribute(conv2_kernel, cudaFuncAttributeMaxDynamicSharedMemorySize, SMEM_TOTAL2);

    prep_w2<<<576, 256>>>(t_w2, f_w2);
    conv1_kernel<<<dim3(49, BATCH, 2), 256, C1_SMEM>>>(x, t_w1, t_b1, f_w1, f_b1);
    conv2_kernel<<<dim3(28, BATCH, 2), 256, SMEM_TOTAL2>>>(t_b2, f_b2);
    head_kernel<<<64, 128>>>(t_wf, t_bf, f_wf, f_bf, out);
    head2_kernel<<<1, 64>>>(out, out_size);
}

// round 15
// speedup vs baseline: 5.2141x; 1.0108x over previous
#include <cuda_runtime.h>
#include <cuda_fp16.h>
#include <cstdint>

#define BATCH 64
typedef unsigned long long ull;
typedef uint32_t u32;

// ---------------------------------------------------------------------------
// Device scratch
// ---------------------------------------------------------------------------
__device__ __half g_h1h[2ULL * BATCH * 112 * 112 * 64]; // NHWC fp16, k-chunk permuted
__device__ __half g_w2h[2 * 9 * 128 * 64];              // [e][tap][oc][icp] fp16
__device__ float  g_partial[2 * BATCH * 28 * 128];      // pooled partials per M-tile
__device__ float  g_flags[BATCH];                       // per-batch use2 flag

// ---------------------------------------------------------------------------
// helpers
// ---------------------------------------------------------------------------
__device__ __forceinline__ ull pack2(float lo, float hi) {
    ull r; asm("mov.b64 %0, {%1,%2};" : "=l"(r) : "f"(lo), "f"(hi)); return r;
}
__device__ __forceinline__ void unpack2(ull v, float& lo, float& hi) {
    asm("mov.b64 {%0,%1}, %2;" : "=f"(lo), "=f"(hi) : "l"(v));
}
__device__ __forceinline__ ull fma2(ull a, ull b, ull c) {
    ull d; asm("fma.rn.f32x2 %0, %1, %2, %3;" : "=l"(d) : "l"(a), "l"(b), "l"(c)); return d;
}
__device__ __forceinline__ u32 smem_u32(const void* p) {
    return (u32)__cvta_generic_to_shared(p);
}
__device__ __forceinline__ void cp16(u32 dst, const void* src) {
    asm volatile("cp.async.cg.shared.global [%0], [%1], 16;" :: "r"(dst), "l"(src));
}
__device__ __forceinline__ void cp_commit() {
    asm volatile("cp.async.commit_group;" ::: "memory");
}
template<int N> __device__ __forceinline__ void cp_wait() {
    asm volatile("cp.async.wait_group %0;" :: "n"(N) : "memory");
}
__device__ __forceinline__ void lds2(u32& x, u32& y, u32 addr) {
    asm volatile("ld.shared.v2.b32 {%0,%1}, [%2];" : "=r"(x), "=r"(y) : "r"(addr));
}
// fp16 mma m16n8k16, fp32 accumulate. A regs order: {row,k0},{row+8,k0},{row,k8},{row+8,k8}
__device__ __forceinline__ void mma_f16(float* c, u32 a0, u32 a1, u32 a2, u32 a3,
                                        u32 b0, u32 b1) {
    asm volatile(
        "mma.sync.aligned.m16n8k16.row.col.f32.f16.f16.f32 "
        "{%0,%1,%2,%3}, {%4,%5,%6,%7}, {%8,%9}, {%0,%1,%2,%3};"
        : "+f"(c[0]), "+f"(c[1]), "+f"(c[2]), "+f"(c[3])
        : "r"(a0), "r"(a1), "r"(a2), "r"(a3), "r"(b0), "r"(b1));
}

// k-chunk permutation: within each 16-half group, stored 2-half chunk q holds
// original chunk c = (q>>1) | ((q&1)<<2), so frag pairs (c, c+4) are adjacent.
__device__ __forceinline__ int perm16(int p) {
    int g = p & ~15, h = p & 15, q = h >> 1, bb = h & 1;
    int c = (q >> 1) | ((q & 1) << 2);
    return g | (c << 1) | bb;
}

// ---------------------------------------------------------------------------
// dummy: shifts the ncu capture slot so conv2 lands on launch #4
// ---------------------------------------------------------------------------
__global__ void dummy_kernel() {}

// ---------------------------------------------------------------------------
// prep: conv2 weights [oc][ic][3][3] -> [e][tap][oc][icp] fp16
// ---------------------------------------------------------------------------
__global__ void prep_w2(const float* __restrict__ tw2, const float* __restrict__ fw2)
{
    const int i = blockIdx.x * 256 + threadIdx.x;   // < 147456
    const int e = i / 73728;
    const int r = i - e * 73728;
    const int tap = r / 8192;
    const int r2 = r - tap * 8192;
    const int oc = r2 >> 6, icp = r2 & 63;
    const int ic = perm16(icp);
    const float* w = e ? fw2 : tw2;
    g_w2h[i] = __float2half(w[oc * 576 + ic * 9 + tap]);
}

// ---------------------------------------------------------------------------
// conv1 + ReLU (f32x2) -> NHWC permuted fp16, smem-staged coalesced stores.
// grid=(49, BATCH, 2), 256 threads, dyn smem 256*36*4 = 36864 B
// ---------------------------------------------------------------------------
#define C1_SMEM (256 * 36 * 4)

__global__ __launch_bounds__(256) void conv1_kernel(const float* __restrict__ x,
                                                    const float* __restrict__ wt,
                                                    const float* __restrict__ bt,
                                                    const float* __restrict__ wf,
                                                    const float* __restrict__ bf)
{
    __shared__ float ws[27 * 64];   // [k 27][oc 64]
    __shared__ float bs[64];
    extern __shared__ u32 so[];     // [256 pos][36 u32] (32 data + 4 pad)
    const int tid = threadIdx.x;
    const int b = blockIdx.y, e = blockIdx.z;
    const float* w = e ? wf : wt;
    const float* bias = e ? bf : bt;

    for (int i = tid; i < 27 * 64; i += 256) {
        int oc = i / 27, k = i % 27;
        ws[k * 64 + oc] = w[i];
    }
    if (tid < 64) bs[tid] = bias[tid];
    __syncthreads();

    const int pos = blockIdx.x * 256 + tid;    // 0..12543
    const int oh = pos / 112, ow = pos % 112;
    const int ih0 = oh * 2, iw0 = ow * 2;
    const bool bh = (oh < 111), bw = (ow < 111);

    ull pin[27];
    const float* xb = x + (size_t)b * (3 * 224 * 224);
    #pragma unroll
    for (int ic = 0; ic < 3; ++ic) {
        const float* p = xb + ic * (224 * 224) + ih0 * 224 + iw0;
        #pragma unroll
        for (int kh = 0; kh < 3; ++kh) {
            #pragma unroll
            for (int kw = 0; kw < 3; ++kw) {
                bool ok = (kh < 2 || bh) && (kw < 2 || bw);
                float v = ok ? p[kh * 224 + kw] : 0.0f;
                pin[ic * 9 + kh * 3 + kw] = pack2(v, v);
            }
        }
    }

    float ov[64];
    #pragma unroll
    for (int occ = 0; occ < 4; ++occ) {
        ull acc[8];
        #pragma unroll
        for (int j = 0; j < 8; ++j)
            acc[j] = pack2(bs[occ * 16 + 2 * j], bs[occ * 16 + 2 * j + 1]);
        #pragma unroll
        for (int k = 0; k < 27; ++k) {
            const ull* w2 = (const ull*)(ws + k * 64 + occ * 16);
            #pragma unroll
            for (int j = 0; j < 8; ++j)
                acc[j] = fma2(pin[k], w2[j], acc[j]);
        }
        #pragma unroll
        for (int j = 0; j < 8; ++j) {
            float lo, hi; unpack2(acc[j], lo, hi);
            ov[occ * 16 + 2 * j]     = fmaxf(lo, 0.0f);
            ov[occ * 16 + 2 * j + 1] = fmaxf(hi, 0.0f);
        }
    }
    // pack to permuted fp16: stored u32 chunk i holds orig halves (o0, o0+1)
    #pragma unroll
    for (int i = 0; i < 32; ++i) {
        const int g = i >> 3, q = i & 7;
        const int c = (q >> 1) | ((q & 1) << 2);
        const int o0 = g * 16 + c * 2;
        half2 h2 = __floats2half2_rn(ov[o0], ov[o0 + 1]);
        so[tid * 36 + i] = *(u32*)&h2;
    }
    __syncthreads();

    // coalesced: block's 256 pos x 64 halves = 32KB contiguous span
    uint4* out4 = (uint4*)(g_h1h + ((size_t)(e * BATCH + b) * 12544
                                    + (size_t)blockIdx.x * 256) * 64);
    #pragma unroll
    for (int k = 0; k < 8; ++k) {
        const int f = k * 256 + tid;          // uint4 index 0..2047
        const int lpos = f >> 3, c4 = (f & 7) * 4;
        out4[f] = *(const uint4*)(so + lpos * 36 + c4);
    }
}

// ---------------------------------------------------------------------------
// conv2: implicit GEMM, fp16 mma.sync m16n8k16 + fused bias/ReLU/GAP.
// Tile M=128 (2 oh x 64 ow; ow>=56 padded), N=128 oc, K=9 taps x 64 ic.
// 8 warps, warp tile 32x64. grid=(28, BATCH, 2), 256 thr, 2 CTAs/SM.
// Single barrier per tap: top barrier of iter t guarantees all warps are done
// with mma(t-1), so issuing load(t+1) into buf[(t+1)&1] == buf[(t-1)&1] right
// after it is WAR-safe; cp_wait<0> before the barrier delivers tap t's data.
// ---------------------------------------------------------------------------
#define ROWB  160
#define AST2  (128 * ROWB)          // 20480 per stage
#define B_OFF (2 * AST2)            // 40960
#define MISC  (4 * AST2)            // 81920
#define SMEM_TOTAL2 (MISC + 512 + 4096)

__global__ __launch_bounds__(256, 2) void conv2_kernel(const float* __restrict__ bias_t,
                                                       const float* __restrict__ bias_f)
{
    extern __shared__ __align__(256) char smem[];
    const int tid = threadIdx.x;
    const int wid = tid >> 5, lane = tid & 31;
    const int tile = blockIdx.x, b = blockIdx.y, e = blockIdx.z;
    const u32 sb = smem_u32(smem);

    float* bias_s = (float*)(smem + MISC);
    float* wsum   = (float*)(smem + MISC + 512);   // [8 warps][128]

    if (tid < 128) bias_s[tid] = (e ? bias_f : bias_t)[tid];

    // loader: 2 threads per row, 64B (4 cp16) each
    const int m = tid >> 1;
    const int half = tid & 1;
    const int ohl = m >> 6, owl = m & 63;
    const size_t img = (size_t)(e * BATCH + b) * (112 * 112 * 64);
    const __half* wt_base = g_w2h + (size_t)e * (9 * 128 * 64) + (size_t)m * 64 + half * 32;
    const u32 a_row = sb + m * ROWB + half * 64;
    const u32 b_row = sb + B_OFF + m * ROWB + half * 64;

    auto load_tap = [&](int tap, int stage) {
        const int kh = tap / 3, kw = tap - kh * 3;
        const int ih = 4 * tile + 2 * ohl + kh;
        const int iw = 2 * owl + kw;
        const u32 a_s = a_row + stage * AST2;
        if (ih < 112 && iw < 112) {
            const __half* src = g_h1h + img + ((size_t)ih * 112 + iw) * 64 + half * 32;
            #pragma unroll
            for (int j = 0; j < 4; ++j) cp16(a_s + j * 16, src + j * 8);
        } else {
            uint4* p = (uint4*)(smem + stage * AST2 + m * ROWB + half * 64);
            const uint4 z = make_uint4(0, 0, 0, 0);
            #pragma unroll
            for (int j = 0; j < 4; ++j) p[j] = z;
        }
        const u32 b_s = b_row + stage * AST2;
        const __half* bsrc = wt_base + (size_t)tap * 8192;
        #pragma unroll
        for (int j = 0; j < 4; ++j) cp16(b_s + j * 16, bsrc + j * 8);
    };

    const int warp_m = (wid & 3) * 32;
    const int warp_n = (wid >> 2) * 64;
    const u32 frag_off = (u32)((lane >> 2) * ROWB + (lane & 3) * 8);

    float acc[2][8][4];
    #pragma unroll
    for (int i = 0; i < 2; ++i)
        #pragma unroll
        for (int j = 0; j < 8; ++j)
            #pragma unroll
            for (int t = 0; t < 4; ++t) acc[i][j][t] = 0.0f;

    load_tap(0, 0); cp_commit();

    for (int t = 0; t < 9; ++t) {
        const int stage = t & 1;
        cp_wait<0>();            // tap t's group (only one ever outstanding)
        __syncthreads();         // data visible + all warps done with mma(t-1)
        if (t < 8) { load_tap(t + 1, stage ^ 1); cp_commit(); }  // overlaps mma(t)

        const u32 abase = sb + stage * AST2 + warp_m * ROWB + frag_off;
        const u32 bbase = sb + B_OFF + stage * AST2 + warp_n * ROWB + frag_off;
        #pragma unroll
        for (int s = 0; s < 4; ++s) {          // 4 x k16 per tap
            u32 X0[2], X1[2], Y0[2], Y1[2];    // {row,k0} {row+8,k0} {row,k8} {row+8,k8}
            #pragma unroll
            for (int i = 0; i < 2; ++i) {
                lds2(X0[i], Y0[i], abase + i * (16 * ROWB) + s * 32);
                lds2(X1[i], Y1[i], abase + i * (16 * ROWB) + 8 * ROWB + s * 32);
            }
            #pragma unroll
            for (int j = 0; j < 8; ++j) {
                u32 B0, B1;
                lds2(B0, B1, bbase + j * (8 * ROWB) + s * 32);
                #pragma unroll
                for (int i = 0; i < 2; ++i)
                    mma_f16(acc[i][j], X0[i], X1[i], Y0[i], Y1[i], B0, B1);
            }
        }
    }

    // epilogue: bias + ReLU + masked pool (ow<56), deterministic
    {
        const int g = lane >> 2, c = lane & 3;
        #pragma unroll
        for (int j = 0; j < 8; ++j) {
            float s0 = 0.0f, s1 = 0.0f;
            const int n0 = warp_n + j * 8 + 2 * c;
            const float bi0 = bias_s[n0], bi1 = bias_s[n0 + 1];
            #pragma unroll
            for (int i = 0; i < 2; ++i) {
                const int rlo = warp_m + i * 16 + g;
                const int rhi = rlo + 8;
                const bool vlo = (rlo & 63) < 56, vhi = (rhi & 63) < 56;
                if (vlo) { s0 += fmaxf(acc[i][j][0] + bi0, 0.0f);
                           s1 += fmaxf(acc[i][j][1] + bi1, 0.0f); }
                if (vhi) { s0 += fmaxf(acc[i][j][2] + bi0, 0.0f);
                           s1 += fmaxf(acc[i][j][3] + bi1, 0.0f); }
            }
            #pragma unroll
            for (int sh = 4; sh < 32; sh <<= 1) {
                s0 += __shfl_down_sync(0xffffffffu, s0, sh);
                s1 += __shfl_down_sync(0xffffffffu, s1, sh);
            }
            if (g == 0) {
                wsum[wid * 128 + n0]     = s0;
                wsum[wid * 128 + n0 + 1] = s1;
            }
        }
    }
    __syncthreads();
    if (tid < 128) {
        const int wbase = (tid < 64) ? 0 : 4;
        float s = 0.0f;
        #pragma unroll
        for (int wq = 0; wq < 4; ++wq) s += wsum[(wbase + wq) * 128 + tid];
        g_partial[(((size_t)e * BATCH + b) * 28 + tile) * 128 + tid] = s;
    }
}

// ---------------------------------------------------------------------------
// head: grid=64 blocks (one per batch) x 128 threads (one per channel)
// ---------------------------------------------------------------------------
__global__ void head_kernel(const float* __restrict__ t_wf, const float* __restrict__ t_bf,
                            const float* __restrict__ f_wf, const float* __restrict__ f_bf,
                            float* __restrict__ out)
{
    __shared__ float red[16];
    const int b = blockIdx.x;
    const int c = threadIdx.x;
    const int lane = c & 31, warp = c >> 5;

    const float inv = 1.0f / 3136.0f;
    const size_t tb = (size_t)b * 28 * 128 + c;
    const size_t fb = (size_t)(BATCH + b) * 28 * 128 + c;

    float st = 0.0f, sf = 0.0f;
    #pragma unroll
    for (int tt = 0; tt < 28; ++tt) {
        st += g_partial[tb + (size_t)tt * 128];
        sf += g_partial[fb + (size_t)tt * 128];
    }
    const float gt = st * inv, gf = sf * inv;
    float p0 = gt * t_wf[c * 2 + 0];
    float p1 = gt * t_wf[c * 2 + 1];
    float p2 = gf * f_wf[c * 2 + 0];
    float p3 = gf * f_wf[c * 2 + 1];

    #pragma unroll
    for (int sh = 16; sh > 0; sh >>= 1) {
        p0 += __shfl_down_sync(0xffffffffu, p0, sh);
        p1 += __shfl_down_sync(0xffffffffu, p1, sh);
        p2 += __shfl_down_sync(0xffffffffu, p2, sh);
        p3 += __shfl_down_sync(0xffffffffu, p3, sh);
    }
    if (lane == 0) {
        red[warp * 4 + 0] = p0; red[warp * 4 + 1] = p1;
        red[warp * 4 + 2] = p2; red[warp * 4 + 3] = p3;
    }
    __syncthreads();
    if (c == 0) {
        float tl0 = t_bf[0], tl1 = t_bf[1], fl0 = f_bf[0], fl1 = f_bf[1];
        #pragma unroll
        for (int wq = 0; wq < 4; ++wq) {
            tl0 += red[wq * 4 + 0]; tl1 += red[wq * 4 + 1];
            fl0 += red[wq * 4 + 2]; fl1 += red[wq * 4 + 3];
        }
        const float mx = fmaxf(tl0, tl1);
        const float e0 = expf(tl0 - mx), e1 = expf(tl1 - mx);
        const float conf = fmaxf(e0, e1) / (e0 + e1);
        const bool use2 = (conf <= 0.9f);
        out[b * 2 + 0] = use2 ? 0.7f * tl0 + 0.3f * fl0 : tl0;
        out[b * 2 + 1] = use2 ? 0.7f * tl1 + 0.3f * fl1 : tl1;
        g_flags[b] = use2 ? 1.0f : 0.0f;
    }
}

__global__ void head2_kernel(float* __restrict__ out, int out_size)
{
    __shared__ float s[64];
    const int t = threadIdx.x;
    s[t] = g_flags[t];
    __syncthreads();
    if (t == 0) {
        float acc = 0.0f;
        #pragma unroll
        for (int i = 0; i < 64; ++i) acc += s[i];
        if (out_size > 128) out[128] = acc * (1.0f / 64.0f);
    }
}

// ---------------------------------------------------------------------------
extern "C" void kernel_launch(void* const* d_in, const int* in_sizes, int n_in,
                              void* d_out, int out_size)
{
    const float* x    = (const float*)d_in[0];
    const float* t_w1 = (const float*)d_in[1];
    const float* t_b1 = (const float*)d_in[2];
    const float* t_w2 = (const float*)d_in[3];
    const float* t_b2 = (const float*)d_in[4];
    const float* t_wf = (const float*)d_in[5];
    const float* t_bf = (const float*)d_in[6];
    const float* f_w1 = (const float*)d_in[7];
    const float* f_b1 = (const float*)d_in[8];
    const float* f_w2 = (const float*)d_in[9];
    const float* f_b2 = (const float*)d_in[10];
    const float* f_wf = (const float*)d_in[11];
    const float* f_bf = (const float*)d_in[12];
    float* out = (float*)d_out;

    cudaFuncSetAttribute(conv1_kernel, cudaFuncAttributeMaxDynamicSharedMemorySize, C1_SMEM);
    cudaFuncSetAttribute(conv2_kernel, cudaFuncAttributeMaxDynamicSharedMemorySize, SMEM_TOTAL2);

    prep_w2<<<576, 256>>>(t_w2, f_w2);                               // launch 1
    dummy_kernel<<<1, 1>>>();                                        // launch 2 (capture shift)
    conv1_kernel<<<dim3(49, BATCH, 2), 256, C1_SMEM>>>(x, t_w1, t_b1, f_w1, f_b1);   // 3
    conv2_kernel<<<dim3(28, BATCH, 2), 256, SMEM_TOTAL2>>>(t_b2, f_b2);              // 4 <- ncu
    head_kernel<<<64, 128>>>(t_wf, t_bf, f_wf, f_bf, out);           // 5
    head2_kernel<<<1, 64>>>(out, out_size);                          // 6
}

// round 17
// speedup vs baseline: 5.7007x; 1.0933x over previous
#include <cuda_runtime.h>
#include <cuda_fp16.h>
#include <cstdint>

#define BATCH 64
typedef unsigned long long ull;
typedef uint32_t u32;

// ---------------------------------------------------------------------------
// Device scratch
// ---------------------------------------------------------------------------
__device__ __half g_h1h[2ULL * BATCH * 112 * 112 * 64]; // NHWC fp16 (natural order)
__device__ __half g_w2h[2 * 9 * 128 * 64];              // [e][tap][oc][ic] fp16
__device__ float  g_partial[2 * BATCH * 28 * 128];      // pooled partials per M-tile
__device__ float  g_flags[BATCH];                       // per-batch use2 flag

// ---------------------------------------------------------------------------
// helpers
// ---------------------------------------------------------------------------
__device__ __forceinline__ ull pack2(float lo, float hi) {
    ull r; asm("mov.b64 %0, {%1,%2};" : "=l"(r) : "f"(lo), "f"(hi)); return r;
}
__device__ __forceinline__ void unpack2(ull v, float& lo, float& hi) {
    asm("mov.b64 {%0,%1}, %2;" : "=f"(lo), "=f"(hi) : "l"(v));
}
__device__ __forceinline__ ull fma2(ull a, ull b, ull c) {
    ull d; asm("fma.rn.f32x2 %0, %1, %2, %3;" : "=l"(d) : "l"(a), "l"(b), "l"(c)); return d;
}
__device__ __forceinline__ u32 smem_u32(const void* p) {
    return (u32)__cvta_generic_to_shared(p);
}
__device__ __forceinline__ void cp16(u32 dst, const void* src) {
    asm volatile("cp.async.cg.shared.global [%0], [%1], 16;" :: "r"(dst), "l"(src));
}
__device__ __forceinline__ void cp_commit() {
    asm volatile("cp.async.commit_group;" ::: "memory");
}
template<int N> __device__ __forceinline__ void cp_wait() {
    asm volatile("cp.async.wait_group %0;" :: "n"(N) : "memory");
}
// ldmatrix x4: four 8x8 b16 tiles; lane groups 0-7/8-15/16-23/24-31 give row addrs
__device__ __forceinline__ void ldsm4(u32& r0, u32& r1, u32& r2, u32& r3, u32 addr) {
    asm volatile("ldmatrix.sync.aligned.m8n8.x4.shared.b16 {%0,%1,%2,%3}, [%4];"
                 : "=r"(r0), "=r"(r1), "=r"(r2), "=r"(r3) : "r"(addr));
}
// fp16 mma m16n8k16, fp32 accumulate
__device__ __forceinline__ void mma_f16(float* c, u32 a0, u32 a1, u32 a2, u32 a3,
                                        u32 b0, u32 b1) {
    asm volatile(
        "mma.sync.aligned.m16n8k16.row.col.f32.f16.f16.f32 "
        "{%0,%1,%2,%3}, {%4,%5,%6,%7}, {%8,%9}, {%0,%1,%2,%3};"
        : "+f"(c[0]), "+f"(c[1]), "+f"(c[2]), "+f"(c[3])
        : "r"(a0), "r"(a1), "r"(a2), "r"(a3), "r"(b0), "r"(b1));
}

// ---------------------------------------------------------------------------
// dummy: keeps conv2 on ncu capture slot #4
// ---------------------------------------------------------------------------
__global__ void dummy_kernel() {}

// ---------------------------------------------------------------------------
// prep: conv2 weights [oc][ic][3][3] -> [e][tap][oc][ic] fp16 (natural order)
// ---------------------------------------------------------------------------
__global__ void prep_w2(const float* __restrict__ tw2, const float* __restrict__ fw2)
{
    const int i = blockIdx.x * 256 + threadIdx.x;   // < 147456
    const int e = i / 73728;
    const int r = i - e * 73728;
    const int tap = r / 8192;
    const int r2 = r - tap * 8192;
    const int oc = r2 >> 6, ic = r2 & 63;
    const float* w = e ? fw2 : tw2;
    g_w2h[i] = __float2half(w[oc * 576 + ic * 9 + tap]);
}

// ---------------------------------------------------------------------------
// conv1 + ReLU (f32x2) -> NHWC fp16 (natural order), smem-staged stores.
// grid=(49, BATCH, 2), 256 threads, dyn smem 256*36*4 = 36864 B
// ---------------------------------------------------------------------------
#define C1_SMEM (256 * 36 * 4)

__global__ __launch_bounds__(256) void conv1_kernel(const float* __restrict__ x,
                                                    const float* __restrict__ wt,
                                                    const float* __restrict__ bt,
                                                    const float* __restrict__ wf,
                                                    const float* __restrict__ bf)
{
    __shared__ float ws[27 * 64];   // [k 27][oc 64]
    __shared__ float bs[64];
    extern __shared__ u32 so[];     // [256 pos][36 u32] (32 data + 4 pad)
    const int tid = threadIdx.x;
    const int b = blockIdx.y, e = blockIdx.z;
    const float* w = e ? wf : wt;
    const float* bias = e ? bf : bt;

    for (int i = tid; i < 27 * 64; i += 256) {
        int oc = i / 27, k = i % 27;
        ws[k * 64 + oc] = w[i];
    }
    if (tid < 64) bs[tid] = bias[tid];
    __syncthreads();

    const int pos = blockIdx.x * 256 + tid;    // 0..12543
    const int oh = pos / 112, ow = pos % 112;
    const int ih0 = oh * 2, iw0 = ow * 2;
    const bool bh = (oh < 111), bw = (ow < 111);

    ull pin[27];
    const float* xb = x + (size_t)b * (3 * 224 * 224);
    #pragma unroll
    for (int ic = 0; ic < 3; ++ic) {
        const float* p = xb + ic * (224 * 224) + ih0 * 224 + iw0;
        #pragma unroll
        for (int kh = 0; kh < 3; ++kh) {
            #pragma unroll
            for (int kw = 0; kw < 3; ++kw) {
                bool ok = (kh < 2 || bh) && (kw < 2 || bw);
                float v = ok ? p[kh * 224 + kw] : 0.0f;
                pin[ic * 9 + kh * 3 + kw] = pack2(v, v);
            }
        }
    }

    float ov[64];
    #pragma unroll
    for (int occ = 0; occ < 4; ++occ) {
        ull acc[8];
        #pragma unroll
        for (int j = 0; j < 8; ++j)
            acc[j] = pack2(bs[occ * 16 + 2 * j], bs[occ * 16 + 2 * j + 1]);
        #pragma unroll
        for (int k = 0; k < 27; ++k) {
            const ull* w2 = (const ull*)(ws + k * 64 + occ * 16);
            #pragma unroll
            for (int j = 0; j < 8; ++j)
                acc[j] = fma2(pin[k], w2[j], acc[j]);
        }
        #pragma unroll
        for (int j = 0; j < 8; ++j) {
            float lo, hi; unpack2(acc[j], lo, hi);
            ov[occ * 16 + 2 * j]     = fmaxf(lo, 0.0f);
            ov[occ * 16 + 2 * j + 1] = fmaxf(hi, 0.0f);
        }
    }
    // natural-order fp16 pack (ldmatrix needs no permutation)
    #pragma unroll
    for (int i = 0; i < 32; ++i) {
        half2 h2 = __floats2half2_rn(ov[2 * i], ov[2 * i + 1]);
        so[tid * 36 + i] = *(u32*)&h2;
    }
    __syncthreads();

    // coalesced: block's 256 pos x 64 halves = 32KB contiguous span
    uint4* out4 = (uint4*)(g_h1h + ((size_t)(e * BATCH + b) * 12544
                                    + (size_t)blockIdx.x * 256) * 64);
    #pragma unroll
    for (int k = 0; k < 8; ++k) {
        const int f = k * 256 + tid;          // uint4 index 0..2047
        const int lpos = f >> 3, c4 = (f & 7) * 4;
        out4[f] = *(const uint4*)(so + lpos * 36 + c4);
    }
}

// ---------------------------------------------------------------------------
// conv2: implicit GEMM, fp16 mma.sync + ldmatrix fragment loads.
// Tile M=128 (2 oh x 64 ow; ow>=56 padded), N=128 oc, K=9 taps x 64 ic.
// 8 warps, warp tile 32x64. grid=(28, BATCH, 2), 256 thr, 2 CTAs/SM.
// ROWB=144: rows at 16r mod 128 -> 8 distinct 16B offsets, conflict-free LDSM.
// Single barrier per tap (WAR-safe as in R11).
// ---------------------------------------------------------------------------
#define ROWB  144
#define AST2  (128 * ROWB)          // 18432 per stage
#define B_OFF (2 * AST2)            // 36864
#define MISC  (4 * AST2)            // 73728
#define SMEM_TOTAL2 (MISC + 512 + 4096)

__global__ __launch_bounds__(256, 2) void conv2_kernel(const float* __restrict__ bias_t,
                                                       const float* __restrict__ bias_f)
{
    extern __shared__ __align__(256) char smem[];
    const int tid = threadIdx.x;
    const int wid = tid >> 5, lane = tid & 31;
    const int tile = blockIdx.x, b = blockIdx.y, e = blockIdx.z;
    const u32 sb = smem_u32(smem);

    float* bias_s = (float*)(smem + MISC);
    float* wsum   = (float*)(smem + MISC + 512);   // [8 warps][128]

    if (tid < 128) bias_s[tid] = (e ? bias_f : bias_t)[tid];

    // loader: 2 threads per row, 64B (4 cp16) each
    const int m = tid >> 1;
    const int half = tid & 1;
    const int ohl = m >> 6, owl = m & 63;
    const size_t img = (size_t)(e * BATCH + b) * (112 * 112 * 64);
    const __half* wt_base = g_w2h + (size_t)e * (9 * 128 * 64) + (size_t)m * 64 + half * 32;
    const u32 a_row = sb + m * ROWB + half * 64;
    const u32 b_row = sb + B_OFF + m * ROWB + half * 64;

    auto load_tap = [&](int tap, int stage) {
        const int kh = tap / 3, kw = tap - kh * 3;
        const int ih = 4 * tile + 2 * ohl + kh;
        const int iw = 2 * owl + kw;
        const u32 a_s = a_row + stage * AST2;
        if (ih < 112 && iw < 112) {
            const __half* src = g_h1h + img + ((size_t)ih * 112 + iw) * 64 + half * 32;
            #pragma unroll
            for (int j = 0; j < 4; ++j) cp16(a_s + j * 16, src + j * 8);
        } else {
            uint4* p = (uint4*)(smem + stage * AST2 + m * ROWB + half * 64);
            const uint4 z = make_uint4(0, 0, 0, 0);
            #pragma unroll
            for (int j = 0; j < 4; ++j) p[j] = z;
        }
        const u32 b_s = b_row + stage * AST2;
        const __half* bsrc = wt_base + (size_t)tap * 8192;
        #pragma unroll
        for (int j = 0; j < 4; ++j) cp16(b_s + j * 16, bsrc + j * 8);
    };

    const int warp_m = (wid & 3) * 32;
    const int warp_n = (wid >> 2) * 64;

    // ldmatrix per-lane row addresses (stage/s offsets added at use)
    const int lq = lane >> 3, lr = lane & 7;
    u32 a_lm[2], b_lm[4];
    #pragma unroll
    for (int i = 0; i < 2; ++i) {
        const int row = warp_m + i * 16 + (lq & 1) * 8 + lr;
        a_lm[i] = sb + (u32)row * ROWB + (lq >> 1) * 16;
    }
    #pragma unroll
    for (int jp = 0; jp < 4; ++jp) {
        const int n = warp_n + jp * 16 + (lq >> 1) * 8 + lr;
        b_lm[jp] = sb + B_OFF + (u32)n * ROWB + (lq & 1) * 16;
    }

    float acc[2][8][4];
    #pragma unroll
    for (int i = 0; i < 2; ++i)
        #pragma unroll
        for (int j = 0; j < 8; ++j)
            #pragma unroll
            for (int t = 0; t < 4; ++t) acc[i][j][t] = 0.0f;

    load_tap(0, 0); cp_commit();

    for (int t = 0; t < 9; ++t) {
        const int stage = t & 1;
        cp_wait<0>();            // tap t's data landed
        __syncthreads();         // + all warps done with mma(t-1)
        if (t < 8) { load_tap(t + 1, stage ^ 1); cp_commit(); }  // overlaps mma(t)

        const u32 sofs = (u32)stage * AST2;
        #pragma unroll
        for (int s = 0; s < 4; ++s) {          // 4 x k16 per tap
            u32 A[2][4];
            ldsm4(A[0][0], A[0][1], A[0][2], A[0][3], a_lm[0] + sofs + s * 32);
            ldsm4(A[1][0], A[1][1], A[1][2], A[1][3], a_lm[1] + sofs + s * 32);
            #pragma unroll
            for (int jp = 0; jp < 4; ++jp) {
                u32 B0, B1, B2, B3;
                ldsm4(B0, B1, B2, B3, b_lm[jp] + sofs + s * 32);
                mma_f16(acc[0][2 * jp],     A[0][0], A[0][1], A[0][2], A[0][3], B0, B1);
                mma_f16(acc[1][2 * jp],     A[1][0], A[1][1], A[1][2], A[1][3], B0, B1);
                mma_f16(acc[0][2 * jp + 1], A[0][0], A[0][1], A[0][2], A[0][3], B2, B3);
                mma_f16(acc[1][2 * jp + 1], A[1][0], A[1][1], A[1][2], A[1][3], B2, B3);
            }
        }
    }

    // epilogue: bias + ReLU + masked pool (ow<56), deterministic
    {
        const int g = lane >> 2, c = lane & 3;
        #pragma unroll
        for (int j = 0; j < 8; ++j) {
            float s0 = 0.0f, s1 = 0.0f;
            const int n0 = warp_n + j * 8 + 2 * c;
            const float bi0 = bias_s[n0], bi1 = bias_s[n0 + 1];
            #pragma unroll
            for (int i = 0; i < 2; ++i) {
                const int rlo = warp_m + i * 16 + g;
                const int rhi = rlo + 8;
                const bool vlo = (rlo & 63) < 56, vhi = (rhi & 63) < 56;
                if (vlo) { s0 += fmaxf(acc[i][j][0] + bi0, 0.0f);
                           s1 += fmaxf(acc[i][j][1] + bi1, 0.0f); }
                if (vhi) { s0 += fmaxf(acc[i][j][2] + bi0, 0.0f);
                           s1 += fmaxf(acc[i][j][3] + bi1, 0.0f); }
            }
            #pragma unroll
            for (int sh = 4; sh < 32; sh <<= 1) {
                s0 += __shfl_down_sync(0xffffffffu, s0, sh);
                s1 += __shfl_down_sync(0xffffffffu, s1, sh);
            }
            if (g == 0) {
                wsum[wid * 128 + n0]     = s0;
                wsum[wid * 128 + n0 + 1] = s1;
            }
        }
    }
    __syncthreads();
    if (tid < 128) {
        const int wbase = (tid < 64) ? 0 : 4;
        float s = 0.0f;
        #pragma unroll
        for (int wq = 0; wq < 4; ++wq) s += wsum[(wbase + wq) * 128 + tid];
        g_partial[(((size_t)e * BATCH + b) * 28 + tile) * 128 + tid] = s;
    }
}

// ---------------------------------------------------------------------------
// head: grid=64 blocks (one per batch) x 128 threads (one per channel)
// ---------------------------------------------------------------------------
__global__ void head_kernel(const float* __restrict__ t_wf, const float* __restrict__ t_bf,
                            const float* __restrict__ f_wf, const float* __restrict__ f_bf,
                            float* __restrict__ out)
{
    __shared__ float red[16];
    const int b = blockIdx.x;
    const int c = threadIdx.x;
    const int lane = c & 31, warp = c >> 5;

    const float inv = 1.0f / 3136.0f;
    const size_t tb = (size_t)b * 28 * 128 + c;
    const size_t fb = (size_t)(BATCH + b) * 28 * 128 + c;

    float st = 0.0f, sf = 0.0f;
    #pragma unroll
    for (int tt = 0; tt < 28; ++tt) {
        st += g_partial[tb + (size_t)tt * 128];
        sf += g_partial[fb + (size_t)tt * 128];
    }
    const float gt = st * inv, gf = sf * inv;
    float p0 = gt * t_wf[c * 2 + 0];
    float p1 = gt * t_wf[c * 2 + 1];
    float p2 = gf * f_wf[c * 2 + 0];
    float p3 = gf * f_wf[c * 2 + 1];

    #pragma unroll
    for (int sh = 16; sh > 0; sh >>= 1) {
        p0 += __shfl_down_sync(0xffffffffu, p0, sh);
        p1 += __shfl_down_sync(0xffffffffu, p1, sh);
        p2 += __shfl_down_sync(0xffffffffu, p2, sh);
        p3 += __shfl_down_sync(0xffffffffu, p3, sh);
    }
    if (lane == 0) {
        red[warp * 4 + 0] = p0; red[warp * 4 + 1] = p1;
        red[warp * 4 + 2] = p2; red[warp * 4 + 3] = p3;
    }
    __syncthreads();
    if (c == 0) {
        float tl0 = t_bf[0], tl1 = t_bf[1], fl0 = f_bf[0], fl1 = f_bf[1];
        #pragma unroll
        for (int wq = 0; wq < 4; ++wq) {
            tl0 += red[wq * 4 + 0]; tl1 += red[wq * 4 + 1];
            fl0 += red[wq * 4 + 2]; fl1 += red[wq * 4 + 3];
        }
        const float mx = fmaxf(tl0, tl1);
        const float e0 = expf(tl0 - mx), e1 = expf(tl1 - mx);
        const float conf = fmaxf(e0, e1) / (e0 + e1);
        const bool use2 = (conf <= 0.9f);
        out[b * 2 + 0] = use2 ? 0.7f * tl0 + 0.3f * fl0 : tl0;
        out[b * 2 + 1] = use2 ? 0.7f * tl1 + 0.3f * fl1 : tl1;
        g_flags[b] = use2 ? 1.0f : 0.0f;
    }
}

__global__ void head2_kernel(float* __restrict__ out, int out_size)
{
    __shared__ float s[64];
    const int t = threadIdx.x;
    s[t] = g_flags[t];
    __syncthreads();
    if (t == 0) {
        float acc = 0.0f;
        #pragma unroll
        for (int i = 0; i < 64; ++i) acc += s[i];
        if (out_size > 128) out[128] = acc * (1.0f / 64.0f);
    }
}

// ---------------------------------------------------------------------------
extern "C" void kernel_launch(void* const* d_in, const int* in_sizes, int n_in,
                              void* d_out, int out_size)
{
    const float* x    = (const float*)d_in[0];
    const float* t_w1 = (const float*)d_in[1];
    const float* t_b1 = (const float*)d_in[2];
    const float* t_w2 = (const float*)d_in[3];
    const float* t_b2 = (const float*)d_in[4];
    const float* t_wf = (const float*)d_in[5];
    const float* t_bf = (const float*)d_in[6];
    const float* f_w1 = (const float*)d_in[7];
    const float* f_b1 = (const float*)d_in[8];
    const float* f_w2 = (const float*)d_in[9];
    const float* f_b2 = (const float*)d_in[10];
    const float* f_wf = (const float*)d_in[11];
    const float* f_bf = (const float*)d_in[12];
    float* out = (float*)d_out;

    cudaFuncSetAttribute(conv1_kernel, cudaFuncAttributeMaxDynamicSharedMemorySize, C1_SMEM);
    cudaFuncSetAttribute(conv2_kernel, cudaFuncAttributeMaxDynamicSharedMemorySize, SMEM_TOTAL2);

    prep_w2<<<576, 256>>>(t_w2, f_w2);                               // launch 1
    dummy_kernel<<<1, 1>>>();                                        // launch 2 (capture shift)
    conv1_kernel<<<dim3(49, BATCH, 2), 256, C1_SMEM>>>(x, t_w1, t_b1, f_w1, f_b1);   // 3
    conv2_kernel<<<dim3(28, BATCH, 2), 256, SMEM_TOTAL2>>>(t_b2, f_b2);              // 4 <- ncu
    head_kernel<<<64, 128>>>(t_wf, t_bf, f_wf, f_bf, out);           // 5
    head2_kernel<<<1, 64>>>(out, out_size);                          // 6
}